// round 4
// baseline (speedup 1.0000x reference)
#include <cuda_runtime.h>
#include <math.h>

#define N_NODES 10000
#define N_EDGES 160000
#define CDIM 128
#define ADIM 10
#define RDIM 8
#define HDIM 64

#define INV_SQRT_R 0.35355339059327373f
#define INV_SQRT_H 0.125f
#define INV_SQRT_C 0.08838834764831845f
#define INV_SQRT3  0.5773502691896258f
// 1 / (sqrt(2C)*AVG_NEI * sqrt(C*A)) = 1/(256 * sqrt(1280))
#define OUT_SCALE  (1.0f / (256.0f * 35.77708763999664f))

typedef unsigned long long ull;

// ---------------- scratch (device globals; no allocations) ----------------
__device__ float g_h[N_EDGES * HDIM];                 // 41 MB
__device__ float g_tpw[(size_t)N_EDGES * 512];        // 327 MB
__device__ float g_s[N_NODES * CDIM];                 // 5 MB
__device__ float g_v[N_NODES * CDIM * 3];             // 15 MB
__device__ float g_Ms[N_NODES * 256];                 // 10 MB
__device__ float g_Mv[N_NODES * 256 * 3];             // 30 MB
__device__ float g_Wc0[ADIM * 256 * CDIM];            // 1.3 MB
__device__ float g_Wc1[ADIM * 256 * CDIM];            // 1.3 MB
__device__ int   g_cnt[N_NODES];
__device__ int   g_off[N_NODES + 1];
__device__ int   g_cur[N_NODES];
__device__ int   g_csr[N_EDGES];
__device__ int   g_cls[N_NODES];
__device__ int   g_ccnt[ADIM];
__device__ int   g_coff[ADIM + 1];
__device__ int   g_ccur[ADIM];
__device__ int   g_clist[N_NODES];

__device__ __forceinline__ float silu(float x) { return x / (1.0f + expf(-x)); }

// ---------------- packed fp32x2 helpers (Blackwell FFMA2 path) ----------------
__device__ __forceinline__ ull ffma2(ull a, ull b, ull c) {
    ull d;
    asm("fma.rn.f32x2 %0, %1, %2, %3;" : "=l"(d) : "l"(a), "l"(b), "l"(c));
    return d;
}
__device__ __forceinline__ ull dup2(float x) {
    ull d; unsigned xi = __float_as_uint(x);
    asm("mov.b64 %0, {%1, %1};" : "=l"(d) : "r"(xi));
    return d;
}
__device__ __forceinline__ float2 unpack2(ull d) {
    unsigned lo, hi;
    asm("mov.b64 {%0, %1}, %2;" : "=r"(lo), "=r"(hi) : "l"(d));
    return make_float2(__uint_as_float(lo), __uint_as_float(hi));
}

// ---------------- CSR / class-sort plumbing ----------------
__global__ void k_zero() {
    int i = blockIdx.x * 256 + threadIdx.x;
    if (i < N_NODES) g_cnt[i] = 0;
    if (i < ADIM)    g_ccnt[i] = 0;
}

__global__ void k_cls(const float* __restrict__ na) {
    int n = blockIdx.x * 256 + threadIdx.x;
    if (n >= N_NODES) return;
    int a = 0;
    #pragma unroll
    for (int j = 0; j < ADIM; j++)
        if (na[n * ADIM + j] > 0.5f) a = j;
    g_cls[n] = a;
    atomicAdd(&g_ccnt[a], 1);
}

__global__ void k_count(const int* __restrict__ recv) {
    int e = blockIdx.x * 256 + threadIdx.x;   // E % 256 == 0
    atomicAdd(&g_cnt[recv[e]], 1);
}

__global__ void k_scan() {
    __shared__ int sp[1024];
    int t = threadIdx.x;
    const int PER = 10;                        // 1024*10 >= 10000
    int base = t * PER;
    int loc[PER];
    int sum = 0;
    #pragma unroll
    for (int j = 0; j < PER; j++) {
        int idx = base + j;
        int v = (idx < N_NODES) ? g_cnt[idx] : 0;
        loc[j] = sum; sum += v;
    }
    sp[t] = sum;
    __syncthreads();
    for (int d = 1; d < 1024; d <<= 1) {
        int v = (t >= d) ? sp[t - d] : 0;
        __syncthreads();
        sp[t] += v;
        __syncthreads();
    }
    int off = (t > 0) ? sp[t - 1] : 0;
    #pragma unroll
    for (int j = 0; j < PER; j++) {
        int idx = base + j;
        if (idx < N_NODES) { int o = off + loc[j]; g_off[idx] = o; g_cur[idx] = o; }
    }
    if (t == 0) {
        g_off[N_NODES] = sp[1023];
        int s = 0;
        for (int a = 0; a < ADIM; a++) { g_coff[a] = s; g_ccur[a] = s; s += g_ccnt[a]; }
        g_coff[ADIM] = s;
    }
}

__global__ void k_fill(const int* __restrict__ recv) {
    int e = blockIdx.x * 256 + threadIdx.x;
    int r = recv[e];
    int p = atomicAdd(&g_cur[r], 1);
    g_csr[p] = e;
}

__global__ void k_fillc() {
    int n = blockIdx.x * 256 + threadIdx.x;
    if (n >= N_NODES) return;
    int a = g_cls[n];
    int p = atomicAdd(&g_ccur[a], 1);
    g_clist[p] = n;
}

// ---------------- edge MLP: 8 -> 64 -> 64 -> 64 (silu, scaled) ----------------
__global__ __launch_bounds__(128) void k_mlp(const float* __restrict__ ef,
                                             const float* __restrict__ W1,
                                             const float* __restrict__ W2,
                                             const float* __restrict__ W3) {
    __shared__ float sW1[RDIM * HDIM];
    __shared__ float sW2[HDIM * HDIM];
    __shared__ float sW3[HDIM * HDIM];
    int t = threadIdx.x;
    for (int i = t; i < RDIM * HDIM; i += 128) sW1[i] = W1[i];
    for (int i = t; i < HDIM * HDIM; i += 128) { sW2[i] = W2[i]; sW3[i] = W3[i]; }
    __syncthreads();

    int e = blockIdx.x * 128 + t;              // E % 128 == 0
    float x[RDIM];
    #pragma unroll
    for (int k = 0; k < RDIM; k++) x[k] = ef[e * RDIM + k];

    float h1[HDIM];
    #pragma unroll
    for (int j0 = 0; j0 < HDIM; j0 += 4) {
        float a0 = 0, a1 = 0, a2 = 0, a3 = 0;
        #pragma unroll
        for (int k = 0; k < RDIM; k++) {
            float xv = x[k];
            float4 w = *(const float4*)&sW1[k * HDIM + j0];
            a0 = fmaf(xv, w.x, a0); a1 = fmaf(xv, w.y, a1);
            a2 = fmaf(xv, w.z, a2); a3 = fmaf(xv, w.w, a3);
        }
        h1[j0 + 0] = silu(a0 * INV_SQRT_R);
        h1[j0 + 1] = silu(a1 * INV_SQRT_R);
        h1[j0 + 2] = silu(a2 * INV_SQRT_R);
        h1[j0 + 3] = silu(a3 * INV_SQRT_R);
    }

    float h2[HDIM];
    #pragma unroll
    for (int j0 = 0; j0 < HDIM; j0 += 4) {
        float a0 = 0, a1 = 0, a2 = 0, a3 = 0;
        #pragma unroll
        for (int k = 0; k < HDIM; k++) {
            float hv = h1[k];
            float4 w = *(const float4*)&sW2[k * HDIM + j0];
            a0 = fmaf(hv, w.x, a0); a1 = fmaf(hv, w.y, a1);
            a2 = fmaf(hv, w.z, a2); a3 = fmaf(hv, w.w, a3);
        }
        h2[j0 + 0] = silu(a0 * INV_SQRT_H);
        h2[j0 + 1] = silu(a1 * INV_SQRT_H);
        h2[j0 + 2] = silu(a2 * INV_SQRT_H);
        h2[j0 + 3] = silu(a3 * INV_SQRT_H);
    }

    #pragma unroll
    for (int j0 = 0; j0 < HDIM; j0 += 4) {
        float a0 = 0, a1 = 0, a2 = 0, a3 = 0;
        #pragma unroll
        for (int k = 0; k < HDIM; k++) {
            float hv = h2[k];
            float4 w = *(const float4*)&sW3[k * HDIM + j0];
            a0 = fmaf(hv, w.x, a0); a1 = fmaf(hv, w.y, a1);
            a2 = fmaf(hv, w.z, a2); a3 = fmaf(hv, w.w, a3);
        }
        float4 o;
        o.x = silu(a0 * INV_SQRT_H);
        o.y = silu(a1 * INV_SQRT_H);
        o.z = silu(a2 * INV_SQRT_H);
        o.w = silu(a3 * INV_SQRT_H);
        *(float4*)&g_h[e * HDIM + j0] = o;
    }
}

// ---------------- tp_w = h @ W_mlp4 / sqrt(H)  :: (E,64)x(64,512) ----------------
// Packed fp32x2 version. Block: 128 threads, tile 64 edges x 128 outputs.
// Per thread: 8 edges (4 pairs, packed in f32x2) x 8 outputs.
// Edge-pair mapping: pairs at (2*eg + 16*r, +1), r=0..3 -> conflict-free LDS.64.
__global__ __launch_bounds__(128) void k_tpw(const float* __restrict__ W4) {
    __shared__ __align__(16) float sW[HDIM * 128];  // 32 KB : W cols [j0, j0+128)
    __shared__ __align__(16) float sHT[32 * 66];    // 8.25 KB : transposed h half-tile
    int t = threadIdx.x;
    int e0 = blockIdx.x * 64;                       // E % 64 == 0
    int j0 = blockIdx.y * 128;

    for (int i = t; i < HDIM * 128; i += 128) {
        int k = i >> 7, d = i & 127;
        sW[i] = W4[k * 512 + j0 + d];
    }

    int og = t >> 3;          // 0..15 -> output base og*8
    int eg = t & 7;           // 0..7  -> edge pairs at 2*eg + 16*r
    int ob = og * 8;

    ull acc[4][8];
    #pragma unroll
    for (int r = 0; r < 4; r++)
        #pragma unroll
        for (int j = 0; j < 8; j++) acc[r][j] = 0ull;

    for (int kh = 0; kh < 2; kh++) {
        __syncthreads();
        for (int i = t; i < 64 * 32; i += 128) {
            int e = i >> 5, k = i & 31;
            sHT[k * 66 + e] = g_h[(e0 + e) * HDIM + kh * 32 + k];
        }
        __syncthreads();
        #pragma unroll
        for (int k = 0; k < 32; k++) {
            const float* hrow = &sHT[k * 66];
            ull ap[4];
            #pragma unroll
            for (int r = 0; r < 4; r++)
                ap[r] = *(const ull*)(hrow + 2 * eg + 16 * r);
            const float* wrow = &sW[(kh * 32 + k) * 128 + ob];
            float4 w0 = *(const float4*)(wrow);
            float4 w1 = *(const float4*)(wrow + 4);
            ull wd[8];
            wd[0] = dup2(w0.x); wd[1] = dup2(w0.y); wd[2] = dup2(w0.z); wd[3] = dup2(w0.w);
            wd[4] = dup2(w1.x); wd[5] = dup2(w1.y); wd[6] = dup2(w1.z); wd[7] = dup2(w1.w);
            #pragma unroll
            for (int r = 0; r < 4; r++)
                #pragma unroll
                for (int j = 0; j < 8; j++)
                    acc[r][j] = ffma2(ap[r], wd[j], acc[r][j]);
        }
    }

    #pragma unroll
    for (int r = 0; r < 4; r++) {
        float2 u[8];
        #pragma unroll
        for (int j = 0; j < 8; j++) u[j] = unpack2(acc[r][j]);
        int eA = e0 + 2 * eg + 16 * r;
        float* pA = &g_tpw[(size_t)eA * 512 + j0 + ob];
        float* pB = pA + 512;   // edge eA+1
        *(float4*)(pA)     = make_float4(u[0].x * INV_SQRT_H, u[1].x * INV_SQRT_H,
                                         u[2].x * INV_SQRT_H, u[3].x * INV_SQRT_H);
        *(float4*)(pA + 4) = make_float4(u[4].x * INV_SQRT_H, u[5].x * INV_SQRT_H,
                                         u[6].x * INV_SQRT_H, u[7].x * INV_SQRT_H);
        *(float4*)(pB)     = make_float4(u[0].y * INV_SQRT_H, u[1].y * INV_SQRT_H,
                                         u[2].y * INV_SQRT_H, u[3].y * INV_SQRT_H);
        *(float4*)(pB + 4) = make_float4(u[4].y * INV_SQRT_H, u[5].y * INV_SQRT_H,
                                         u[6].y * INV_SQRT_H, u[7].y * INV_SQRT_H);
    }
}

// ---------------- node up-projections s, v ----------------
__global__ __launch_bounds__(256) void k_sv(const float* __restrict__ nf,
                                            const float* __restrict__ Wu0,
                                            const float* __restrict__ Wu1) {
    __shared__ float sW[64 * 128];   // 32 KB
    __shared__ float sX[32 * 64];    // 8 KB
    int t = threadIdx.x;
    int comp = blockIdx.y;
    int n0 = blockIdx.x * 32;
    const float* W = (comp == 0) ? Wu0 : Wu1;
    int nb = (t >> 5) << 2, ob = (t & 31) << 2;
    float acc[4][4] = {};
    for (int k0 = 0; k0 < CDIM; k0 += 64) {
        __syncthreads();
        for (int i = t; i < 64 * 128; i += 256) {
            int kk = i >> 7, d = i & 127;
            sW[i] = W[(k0 + kk) * 128 + d];
        }
        for (int i = t; i < 32 * 64; i += 256) {
            int r = i >> 6, kk = i & 63;
            int n = n0 + r;
            float v = 0.f;
            if (n < N_NODES) {
                if (comp == 0) v = nf[n * 512 + k0 + kk];
                else           v = nf[n * 512 + 128 + (k0 + kk) * 3 + (comp - 1)];
            }
            sX[i] = v;
        }
        __syncthreads();
        #pragma unroll
        for (int kk = 0; kk < 64; kk++) {
            float a0 = sX[(nb + 0) * 64 + kk];
            float a1 = sX[(nb + 1) * 64 + kk];
            float a2 = sX[(nb + 2) * 64 + kk];
            float a3 = sX[(nb + 3) * 64 + kk];
            float4 w = *(const float4*)&sW[kk * 128 + ob];
            acc[0][0] += a0 * w.x; acc[0][1] += a0 * w.y; acc[0][2] += a0 * w.z; acc[0][3] += a0 * w.w;
            acc[1][0] += a1 * w.x; acc[1][1] += a1 * w.y; acc[1][2] += a1 * w.z; acc[1][3] += a1 * w.w;
            acc[2][0] += a2 * w.x; acc[2][1] += a2 * w.y; acc[2][2] += a2 * w.z; acc[2][3] += a2 * w.w;
            acc[3][0] += a3 * w.x; acc[3][1] += a3 * w.y; acc[3][2] += a3 * w.z; acc[3][3] += a3 * w.w;
        }
    }
    #pragma unroll
    for (int r = 0; r < 4; r++) {
        int n = n0 + nb + r;
        if (n >= N_NODES) continue;
        if (comp == 0) {
            float4 o = make_float4(acc[r][0] * INV_SQRT_C, acc[r][1] * INV_SQRT_C,
                                   acc[r][2] * INV_SQRT_C, acc[r][3] * INV_SQRT_C);
            *(float4*)&g_s[n * 128 + ob] = o;
        } else {
            #pragma unroll
            for (int c = 0; c < 4; c++)
                g_v[n * 384 + (ob + c) * 3 + (comp - 1)] = acc[r][c] * INV_SQRT_C;
        }
    }
}

// ---------------- fused weights: Wc[a] = W_lin @ W_skip[:, a, :] ----------------
__global__ __launch_bounds__(256) void k_wc(const float* __restrict__ Wl0,
                                            const float* __restrict__ Wl1,
                                            const float* __restrict__ Wsk0,
                                            const float* __restrict__ Wsk1) {
    __shared__ float sSk[64 * 128];  // 32 KB
    __shared__ float sWl[16 * 64];   // 4 KB
    int t = threadIdx.x;
    int c0 = blockIdx.x * 16;
    int a = blockIdx.y;
    int pair = blockIdx.z;
    const float* Wl  = pair ? Wl1  : Wl0;
    const float* Wsk = pair ? Wsk1 : Wsk0;
    float* Wc = pair ? g_Wc1 : g_Wc0;
    int d = t & 127, half = t >> 7;
    float acc[8] = {};
    for (int m0 = 0; m0 < 128; m0 += 64) {
        __syncthreads();
        for (int i = t; i < 64 * 128; i += 256) {
            int mm = i >> 7, dd = i & 127;
            sSk[i] = Wsk[((m0 + mm) * ADIM + a) * 128 + dd];
        }
        for (int i = t; i < 16 * 64; i += 256) {
            int cc = i >> 6, mm = i & 63;
            sWl[i] = Wl[(c0 + cc) * 128 + m0 + mm];
        }
        __syncthreads();
        #pragma unroll 8
        for (int m = 0; m < 64; m++) {
            float sk = sSk[m * 128 + d];
            #pragma unroll
            for (int j = 0; j < 8; j++) {
                int cc = half + 2 * j;
                acc[j] = fmaf(sWl[cc * 64 + m], sk, acc[j]);
            }
        }
    }
    #pragma unroll
    for (int j = 0; j < 8; j++) {
        int c = c0 + half + 2 * j;
        Wc[(a * 256 + c) * 128 + d] = acc[j];
    }
}

// ---------------- edge aggregation: CSR gather into M_s, M_v ----------------
__global__ __launch_bounds__(128) void k_agg(const int* __restrict__ sender,
                                             const float* __restrict__ ea) {
    int n = blockIdx.x;
    int c = threadIdx.x;
    int beg = g_off[n], end = g_off[n + 1];
    float ms1 = 0, ms2 = 0;
    float mv10 = 0, mv11 = 0, mv12 = 0;
    float mv20 = 0, mv21 = 0, mv22 = 0;
    for (int p = beg; p < end; p++) {
        int e = g_csr[p];
        int sj = sender[e];
        float4 y = *(const float4*)&ea[e * 4];
        const float* tw = g_tpw + (size_t)e * 512;
        float ws1 = tw[c], ws2 = tw[128 + c], wv1 = tw[256 + c], wv2 = tw[384 + c];
        float sv = g_s[sj * 128 + c];
        const float* vp = &g_v[sj * 384 + c * 3];
        float v0 = vp[0], v1 = vp[1], v2 = vp[2];
        ms1 = fmaf(ws1 * sv, y.x, ms1);
        float dot = v0 * y.y + v1 * y.z + v2 * y.w;
        ms2 = fmaf(ws2, dot, ms2);
        float a1 = wv1 * sv;
        mv10 = fmaf(a1, y.y, mv10); mv11 = fmaf(a1, y.z, mv11); mv12 = fmaf(a1, y.w, mv12);
        float a2 = wv2 * y.x;
        mv20 = fmaf(a2, v0, mv20); mv21 = fmaf(a2, v1, mv21); mv22 = fmaf(a2, v2, mv22);
    }
    g_Ms[n * 256 + c] = ms1;
    g_Ms[n * 256 + 128 + c] = ms2 * INV_SQRT3;
    float* m1 = &g_Mv[(n * 256 + c) * 3];
    m1[0] = mv10; m1[1] = mv11; m1[2] = mv12;
    float* m2 = &g_Mv[(n * 256 + 128 + c) * 3];
    m2[0] = mv20; m2[1] = mv21; m2[2] = mv22;
}

// ---------------- class-batched output GEMM: out = M @ Wc[a] * OUT_SCALE ----------------
__global__ __launch_bounds__(256) void k_final(float* __restrict__ out) {
    __shared__ float sW[32 * 128];  // 16 KB
    __shared__ float sX[32 * 32];   // 4 KB
    __shared__ int sN[32];
    int t = threadIdx.x;
    int a = blockIdx.z, comp = blockIdx.y;
    int cbeg = g_coff[a], cend = g_coff[a + 1];
    int nt = cend - cbeg;
    int n0 = blockIdx.x * 32;
    if (n0 >= nt) return;
    const float* Wc = (comp == 0) ? g_Wc0 : g_Wc1;
    if (t < 32) {
        int i = n0 + t;
        sN[t] = (i < nt) ? g_clist[cbeg + i] : -1;
    }
    __syncthreads();
    int nb = (t >> 5) << 2, ob = (t & 31) << 2;
    float acc[4][4] = {};
    for (int k0 = 0; k0 < 256; k0 += 32) {
        for (int i = t; i < 32 * 128; i += 256) {
            int kk = i >> 7, dd = i & 127;
            sW[i] = Wc[(a * 256 + k0 + kk) * 128 + dd];
        }
        for (int i = t; i < 32 * 32; i += 256) {
            int r = i >> 5, kk = i & 31;
            int node = sN[r];
            float v = 0.f;
            if (node >= 0) {
                if (comp == 0) v = g_Ms[node * 256 + k0 + kk];
                else           v = g_Mv[(node * 256 + k0 + kk) * 3 + (comp - 1)];
            }
            sX[i] = v;
        }
        __syncthreads();
        #pragma unroll
        for (int kk = 0; kk < 32; kk++) {
            float a0 = sX[(nb + 0) * 32 + kk];
            float a1 = sX[(nb + 1) * 32 + kk];
            float a2 = sX[(nb + 2) * 32 + kk];
            float a3 = sX[(nb + 3) * 32 + kk];
            float4 w = *(const float4*)&sW[kk * 128 + ob];
            acc[0][0] += a0 * w.x; acc[0][1] += a0 * w.y; acc[0][2] += a0 * w.z; acc[0][3] += a0 * w.w;
            acc[1][0] += a1 * w.x; acc[1][1] += a1 * w.y; acc[1][2] += a1 * w.z; acc[1][3] += a1 * w.w;
            acc[2][0] += a2 * w.x; acc[2][1] += a2 * w.y; acc[2][2] += a2 * w.z; acc[2][3] += a2 * w.w;
            acc[3][0] += a3 * w.x; acc[3][1] += a3 * w.y; acc[3][2] += a3 * w.z; acc[3][3] += a3 * w.w;
        }
        __syncthreads();
    }
    #pragma unroll
    for (int r = 0; r < 4; r++) {
        int node = sN[nb + r];
        if (node < 0) continue;
        if (comp == 0) {
            float4 o = make_float4(acc[r][0] * OUT_SCALE, acc[r][1] * OUT_SCALE,
                                   acc[r][2] * OUT_SCALE, acc[r][3] * OUT_SCALE);
            *(float4*)&out[node * 512 + ob] = o;
        } else {
            #pragma unroll
            for (int c = 0; c < 4; c++)
                out[node * 512 + 128 + (ob + c) * 3 + (comp - 1)] = acc[r][c] * OUT_SCALE;
        }
    }
}

// ---------------- launch ----------------
extern "C" void kernel_launch(void* const* d_in, const int* in_sizes, int n_in,
                              void* d_out, int out_size) {
    const float* node_attrs = (const float*)d_in[0];
    const float* node_feats = (const float*)d_in[1];
    const float* edge_attrs = (const float*)d_in[2];
    const float* edge_feats = (const float*)d_in[3];
    const int*   edge_index = (const int*)d_in[4];
    const float* W_up0  = (const float*)d_in[5];
    const float* W_up1  = (const float*)d_in[6];
    const float* W_mlp1 = (const float*)d_in[7];
    const float* W_mlp2 = (const float*)d_in[8];
    const float* W_mlp3 = (const float*)d_in[9];
    const float* W_mlp4 = (const float*)d_in[10];
    const float* W_lin0 = (const float*)d_in[11];
    const float* W_lin1 = (const float*)d_in[12];
    const float* W_skip0 = (const float*)d_in[13];
    const float* W_skip1 = (const float*)d_in[14];
    float* out = (float*)d_out;

    const int* sender = edge_index;            // row 0
    const int* recv   = edge_index + N_EDGES;  // row 1

    k_zero<<<(N_NODES + 255) / 256, 256>>>();
    k_cls<<<(N_NODES + 255) / 256, 256>>>(node_attrs);
    k_count<<<N_EDGES / 256, 256>>>(recv);
    k_scan<<<1, 1024>>>();
    k_fill<<<N_EDGES / 256, 256>>>(recv);
    k_fillc<<<(N_NODES + 255) / 256, 256>>>();

    k_mlp<<<N_EDGES / 128, 128>>>(edge_feats, W_mlp1, W_mlp2, W_mlp3);
    k_tpw<<<dim3(N_EDGES / 64, 4), 128>>>(W_mlp4);
    k_sv<<<dim3((N_NODES + 31) / 32, 4), 256>>>(node_feats, W_up0, W_up1);
    k_wc<<<dim3(16, ADIM, 2), 256>>>(W_lin0, W_lin1, W_skip0, W_skip1);

    k_agg<<<N_NODES, 128>>>(sender, edge_attrs);
    k_final<<<dim3((N_NODES + 31) / 32, 4, ADIM), 256>>>(out);
}

// round 6
// speedup vs baseline: 1.1182x; 1.1182x over previous
#include <cuda_runtime.h>
#include <cuda_bf16.h>
#include <math.h>

#define N_NODES 10000
#define N_EDGES 160000
#define CDIM 128
#define ADIM 10
#define RDIM 8
#define HDIM 64

#define INV_SQRT_R 0.35355339059327373f
#define INV_SQRT_H 0.125f
#define INV_SQRT_C 0.08838834764831845f
#define INV_SQRT3  0.5773502691896258f
// 1 / (sqrt(2C)*AVG_NEI * sqrt(C*A)) = 1/(256 * sqrt(1280))
#define OUT_SCALE  (1.0f / (256.0f * 35.77708763999664f))

// ---------------- scratch (device globals; no allocations) ----------------
__device__ __nv_bfloat16 g_hhi[N_EDGES * HDIM];       // 20 MB
__device__ __nv_bfloat16 g_hlo[N_EDGES * HDIM];       // 20 MB
__device__ __nv_bfloat16 g_W4T_hi[512 * 64];          // 64 KB (W4 transposed, bf16-hi)
__device__ __nv_bfloat16 g_W4T_lo[512 * 64];          // 64 KB
__device__ float g_tpw[(size_t)N_EDGES * 512];        // 327 MB
__device__ float g_s[N_NODES * CDIM];                 // 5 MB
__device__ float g_v[N_NODES * CDIM * 3];             // 15 MB
__device__ float g_Ms[N_NODES * 256];                 // 10 MB
__device__ float g_Mv[N_NODES * 256 * 3];             // 30 MB
__device__ float g_Wc0[ADIM * 256 * CDIM];            // 1.3 MB
__device__ float g_Wc1[ADIM * 256 * CDIM];            // 1.3 MB
__device__ int   g_cnt[N_NODES];
__device__ int   g_off[N_NODES + 1];
__device__ int   g_cur[N_NODES];
__device__ int   g_csr[N_EDGES];
__device__ int   g_cls[N_NODES];
__device__ int   g_coff[ADIM + 1];
__device__ int   g_ccur[ADIM];
__device__ int   g_clist[N_NODES];

__device__ __forceinline__ float silu(float x) { return x / (1.0f + expf(-x)); }

// ---------------- plumbing ----------------
__global__ void k_cls(const float* __restrict__ na) {
    int n = blockIdx.x * 256 + threadIdx.x;
    if (n >= N_NODES) return;
    g_cnt[n] = 0;
    int a = 0;
    #pragma unroll
    for (int j = 0; j < ADIM; j++)
        if (na[n * ADIM + j] > 0.5f) a = j;
    g_cls[n] = a;
}

__global__ void k_count(const int* __restrict__ recv) {
    int e = blockIdx.x * 256 + threadIdx.x;   // E % 256 == 0
    atomicAdd(&g_cnt[recv[e]], 1);
}

__global__ void k_scan() {
    __shared__ int sp[1024];
    __shared__ int bins[ADIM];
    int t = threadIdx.x;
    if (t < ADIM) bins[t] = 0;
    __syncthreads();
    const int PER = 10;
    int base = t * PER;
    int loc[PER];
    int sum = 0;
    #pragma unroll
    for (int j = 0; j < PER; j++) {
        int idx = base + j;
        int v = 0;
        if (idx < N_NODES) {
            v = g_cnt[idx];
            atomicAdd(&bins[g_cls[idx]], 1);
        }
        loc[j] = sum; sum += v;
    }
    sp[t] = sum;
    __syncthreads();
    for (int d = 1; d < 1024; d <<= 1) {
        int v = (t >= d) ? sp[t - d] : 0;
        __syncthreads();
        sp[t] += v;
        __syncthreads();
    }
    int off = (t > 0) ? sp[t - 1] : 0;
    #pragma unroll
    for (int j = 0; j < PER; j++) {
        int idx = base + j;
        if (idx < N_NODES) { int o = off + loc[j]; g_off[idx] = o; g_cur[idx] = o; }
    }
    if (t == 0) {
        g_off[N_NODES] = sp[1023];
        int s = 0;
        for (int a = 0; a < ADIM; a++) { g_coff[a] = s; g_ccur[a] = s; s += bins[a]; }
        g_coff[ADIM] = s;
    }
}

__global__ void k_fill(const int* __restrict__ recv) {
    int i = blockIdx.x * 256 + threadIdx.x;
    if (i < N_EDGES) {
        int r = recv[i];
        int p = atomicAdd(&g_cur[r], 1);
        g_csr[p] = i;
    }
    if (i < N_NODES) {
        int a = g_cls[i];
        int p = atomicAdd(&g_ccur[a], 1);
        g_clist[p] = i;
    }
}

// ---------------- W4 transpose + bf16 hi/lo split (one-shot tiny kernel) ----------------
__global__ void k_w4t(const float* __restrict__ W4) {
    int gid = blockIdx.x * 256 + threadIdx.x;
    if (gid >= 64 * 512) return;
    int k = gid >> 9, n = gid & 511;
    float v = W4[gid];
    __nv_bfloat16 hi = __float2bfloat16(v);
    float lo = v - __bfloat162float(hi);
    g_W4T_hi[n * 64 + k] = hi;
    g_W4T_lo[n * 64 + k] = __float2bfloat16(lo);
}

// ---------------- edge MLP: 8 -> 64 -> 64 -> 64 (silu) -> bf16 hi/lo split ----------------
__global__ __launch_bounds__(128) void k_mlp(const float* __restrict__ ef,
                                             const float* __restrict__ W1,
                                             const float* __restrict__ W2,
                                             const float* __restrict__ W3) {
    __shared__ float sW1[RDIM * HDIM];
    __shared__ float sW2[HDIM * HDIM];
    __shared__ float sW3[HDIM * HDIM];
    int t = threadIdx.x;
    for (int i = t; i < RDIM * HDIM; i += 128) sW1[i] = W1[i];
    for (int i = t; i < HDIM * HDIM; i += 128) { sW2[i] = W2[i]; sW3[i] = W3[i]; }
    __syncthreads();

    int e = blockIdx.x * 128 + t;              // E % 128 == 0
    float x[RDIM];
    #pragma unroll
    for (int k = 0; k < RDIM; k++) x[k] = ef[e * RDIM + k];

    float h1[HDIM];
    #pragma unroll
    for (int j0 = 0; j0 < HDIM; j0 += 4) {
        float a0 = 0, a1 = 0, a2 = 0, a3 = 0;
        #pragma unroll
        for (int k = 0; k < RDIM; k++) {
            float xv = x[k];
            float4 w = *(const float4*)&sW1[k * HDIM + j0];
            a0 = fmaf(xv, w.x, a0); a1 = fmaf(xv, w.y, a1);
            a2 = fmaf(xv, w.z, a2); a3 = fmaf(xv, w.w, a3);
        }
        h1[j0 + 0] = silu(a0 * INV_SQRT_R);
        h1[j0 + 1] = silu(a1 * INV_SQRT_R);
        h1[j0 + 2] = silu(a2 * INV_SQRT_R);
        h1[j0 + 3] = silu(a3 * INV_SQRT_R);
    }

    float h2[HDIM];
    #pragma unroll
    for (int j0 = 0; j0 < HDIM; j0 += 4) {
        float a0 = 0, a1 = 0, a2 = 0, a3 = 0;
        #pragma unroll
        for (int k = 0; k < HDIM; k++) {
            float hv = h1[k];
            float4 w = *(const float4*)&sW2[k * HDIM + j0];
            a0 = fmaf(hv, w.x, a0); a1 = fmaf(hv, w.y, a1);
            a2 = fmaf(hv, w.z, a2); a3 = fmaf(hv, w.w, a3);
        }
        h2[j0 + 0] = silu(a0 * INV_SQRT_H);
        h2[j0 + 1] = silu(a1 * INV_SQRT_H);
        h2[j0 + 2] = silu(a2 * INV_SQRT_H);
        h2[j0 + 3] = silu(a3 * INV_SQRT_H);
    }

    #pragma unroll
    for (int j0 = 0; j0 < HDIM; j0 += 4) {
        float a0 = 0, a1 = 0, a2 = 0, a3 = 0;
        #pragma unroll
        for (int k = 0; k < HDIM; k++) {
            float hv = h2[k];
            float4 w = *(const float4*)&sW3[k * HDIM + j0];
            a0 = fmaf(hv, w.x, a0); a1 = fmaf(hv, w.y, a1);
            a2 = fmaf(hv, w.z, a2); a3 = fmaf(hv, w.w, a3);
        }
        float o0 = silu(a0 * INV_SQRT_H);
        float o1 = silu(a1 * INV_SQRT_H);
        float o2 = silu(a2 * INV_SQRT_H);
        float o3 = silu(a3 * INV_SQRT_H);
        __nv_bfloat16 hb0 = __float2bfloat16(o0), hb1 = __float2bfloat16(o1);
        __nv_bfloat16 hb2 = __float2bfloat16(o2), hb3 = __float2bfloat16(o3);
        __nv_bfloat16 lb0 = __float2bfloat16(o0 - __bfloat162float(hb0));
        __nv_bfloat16 lb1 = __float2bfloat16(o1 - __bfloat162float(hb1));
        __nv_bfloat16 lb2 = __float2bfloat16(o2 - __bfloat162float(hb2));
        __nv_bfloat16 lb3 = __float2bfloat16(o3 - __bfloat162float(hb3));
        *(__nv_bfloat162*)&g_hhi[e * HDIM + j0]     = __halves2bfloat162(hb0, hb1);
        *(__nv_bfloat162*)&g_hhi[e * HDIM + j0 + 2] = __halves2bfloat162(hb2, hb3);
        *(__nv_bfloat162*)&g_hlo[e * HDIM + j0]     = __halves2bfloat162(lb0, lb1);
        *(__nv_bfloat162*)&g_hlo[e * HDIM + j0 + 2] = __halves2bfloat162(lb2, lb3);
    }
}

// ---------------- tp_w = h @ W4 / sqrt(H) via mma.sync bf16x3 ----------------
// CTA: 64 edges x 512 outputs (4 chunks of 128). 4 warps: warp tile 32 edges x 64 out.
// D = Ah@Bh + Ah@Bl + Al@Bh, fp32 accumulate in registers.
// Smem padded to 72 halves/row (36 words): bank = g*36+q mod 32, conflict-free.
#define SA_H 0
#define SA_L 2304
#define SB_H 4608
#define SB_L 9216
#define TPW_WORDS 13824
#define TPW_DYN (TPW_WORDS * 4)

__global__ __launch_bounds__(128) void k_tpw() {
    extern __shared__ unsigned sm[];
    unsigned* sAh = sm + SA_H;
    unsigned* sAl = sm + SA_L;
    unsigned* sBh = sm + SB_H;
    unsigned* sBl = sm + SB_L;

    int t = threadIdx.x, lane = t & 31, wid = t >> 5;
    int e0 = blockIdx.x * 64;                 // E = 2500 * 64
    const unsigned* hhi = (const unsigned*)g_hhi;
    const unsigned* hlo = (const unsigned*)g_hlo;
    const unsigned* bhi = (const unsigned*)g_W4T_hi;
    const unsigned* blo = (const unsigned*)g_W4T_lo;

    // A fill: 64 rows x 32 words (bf16x2), padded stride 36 words
    for (int i = t; i < 64 * 32; i += 128) {
        int row = i >> 5, k2 = i & 31;
        sAh[row * 36 + k2] = hhi[(e0 + row) * 32 + k2];
        sAl[row * 36 + k2] = hlo[(e0 + row) * 32 + k2];
    }

    int g = lane >> 2, q = lane & 3;
    int m0 = (wid >> 1) * 32;
    int n0 = (wid & 1) * 64;

    for (int nh = 0; nh < 4; nh++) {
        __syncthreads();                      // prev readers done (and A fill, iter 0)
        for (int i = t; i < 128 * 32; i += 128) {
            int n = i >> 5, k2 = i & 31;
            sBh[n * 36 + k2] = bhi[(nh * 128 + n) * 32 + k2];
            sBl[n * 36 + k2] = blo[(nh * 128 + n) * 32 + k2];
        }
        __syncthreads();

        float acc[2][8][4];
        #pragma unroll
        for (int mt = 0; mt < 2; mt++)
            #pragma unroll
            for (int nt = 0; nt < 8; nt++)
                #pragma unroll
                for (int j = 0; j < 4; j++) acc[mt][nt][j] = 0.f;

        #pragma unroll
        for (int pass = 0; pass < 3; pass++) {
            const unsigned* A = (pass == 2) ? sAl : sAh;
            const unsigned* B = (pass == 1) ? sBl : sBh;
            #pragma unroll
            for (int kt = 0; kt < 4; kt++) {
                int kw = kt * 8 + q;
                unsigned a[2][4];
                #pragma unroll
                for (int mt = 0; mt < 2; mt++) {
                    int r = m0 + mt * 16 + g;
                    a[mt][0] = A[r * 36 + kw];
                    a[mt][1] = A[(r + 8) * 36 + kw];
                    a[mt][2] = A[r * 36 + kw + 4];
                    a[mt][3] = A[(r + 8) * 36 + kw + 4];
                }
                #pragma unroll
                for (int nt = 0; nt < 8; nt++) {
                    int n = n0 + nt * 8 + g;
                    unsigned b0 = B[n * 36 + kw];
                    unsigned b1 = B[n * 36 + kw + 4];
                    #pragma unroll
                    for (int mt = 0; mt < 2; mt++) {
                        asm volatile(
                            "mma.sync.aligned.m16n8k16.row.col.f32.bf16.bf16.f32 "
                            "{%0,%1,%2,%3}, {%4,%5,%6,%7}, {%8,%9}, {%0,%1,%2,%3};"
                            : "+f"(acc[mt][nt][0]), "+f"(acc[mt][nt][1]),
                              "+f"(acc[mt][nt][2]), "+f"(acc[mt][nt][3])
                            : "r"(a[mt][0]), "r"(a[mt][1]), "r"(a[mt][2]), "r"(a[mt][3]),
                              "r"(b0), "r"(b1));
                    }
                }
            }
        }

        // epilogue: c0,c1 -> (row g, cols q*2,q*2+1); c2,c3 -> row g+8
        #pragma unroll
        for (int mt = 0; mt < 2; mt++) {
            int er = e0 + m0 + mt * 16 + g;
            #pragma unroll
            for (int nt = 0; nt < 8; nt++) {
                int col = nh * 128 + n0 + nt * 8 + q * 2;
                float2 d0 = make_float2(acc[mt][nt][0] * INV_SQRT_H,
                                        acc[mt][nt][1] * INV_SQRT_H);
                float2 d1 = make_float2(acc[mt][nt][2] * INV_SQRT_H,
                                        acc[mt][nt][3] * INV_SQRT_H);
                *(float2*)&g_tpw[(size_t)er * 512 + col]       = d0;
                *(float2*)&g_tpw[(size_t)(er + 8) * 512 + col] = d1;
            }
        }
    }
}

// ---------------- node up-projections s, v ----------------
__global__ __launch_bounds__(256) void k_sv(const float* __restrict__ nf,
                                            const float* __restrict__ Wu0,
                                            const float* __restrict__ Wu1) {
    __shared__ float sW[64 * 128];   // 32 KB
    __shared__ float sX[32 * 64];    // 8 KB
    int t = threadIdx.x;
    int comp = blockIdx.y;
    int n0 = blockIdx.x * 32;
    const float* W = (comp == 0) ? Wu0 : Wu1;
    int nb = (t >> 5) << 2, ob = (t & 31) << 2;
    float acc[4][4] = {};
    for (int k0 = 0; k0 < CDIM; k0 += 64) {
        __syncthreads();
        for (int i = t; i < 64 * 128; i += 256) {
            int kk = i >> 7, d = i & 127;
            sW[i] = W[(k0 + kk) * 128 + d];
        }
        for (int i = t; i < 32 * 64; i += 256) {
            int r = i >> 6, kk = i & 63;
            int n = n0 + r;
            float v = 0.f;
            if (n < N_NODES) {
                if (comp == 0) v = nf[n * 512 + k0 + kk];
                else           v = nf[n * 512 + 128 + (k0 + kk) * 3 + (comp - 1)];
            }
            sX[i] = v;
        }
        __syncthreads();
        #pragma unroll
        for (int kk = 0; kk < 64; kk++) {
            float a0 = sX[(nb + 0) * 64 + kk];
            float a1 = sX[(nb + 1) * 64 + kk];
            float a2 = sX[(nb + 2) * 64 + kk];
            float a3 = sX[(nb + 3) * 64 + kk];
            float4 w = *(const float4*)&sW[kk * 128 + ob];
            acc[0][0] += a0 * w.x; acc[0][1] += a0 * w.y; acc[0][2] += a0 * w.z; acc[0][3] += a0 * w.w;
            acc[1][0] += a1 * w.x; acc[1][1] += a1 * w.y; acc[1][2] += a1 * w.z; acc[1][3] += a1 * w.w;
            acc[2][0] += a2 * w.x; acc[2][1] += a2 * w.y; acc[2][2] += a2 * w.z; acc[2][3] += a2 * w.w;
            acc[3][0] += a3 * w.x; acc[3][1] += a3 * w.y; acc[3][2] += a3 * w.z; acc[3][3] += a3 * w.w;
        }
    }
    #pragma unroll
    for (int r = 0; r < 4; r++) {
        int n = n0 + nb + r;
        if (n >= N_NODES) continue;
        if (comp == 0) {
            float4 o = make_float4(acc[r][0] * INV_SQRT_C, acc[r][1] * INV_SQRT_C,
                                   acc[r][2] * INV_SQRT_C, acc[r][3] * INV_SQRT_C);
            *(float4*)&g_s[n * 128 + ob] = o;
        } else {
            #pragma unroll
            for (int c = 0; c < 4; c++)
                g_v[n * 384 + (ob + c) * 3 + (comp - 1)] = acc[r][c] * INV_SQRT_C;
        }
    }
}

// ---------------- fused weights: Wc[a] = W_lin @ W_skip[:, a, :] ----------------
__global__ __launch_bounds__(256) void k_wc(const float* __restrict__ Wl0,
                                            const float* __restrict__ Wl1,
                                            const float* __restrict__ Wsk0,
                                            const float* __restrict__ Wsk1) {
    __shared__ float sSk[64 * 128];  // 32 KB
    __shared__ float sWl[16 * 64];   // 4 KB
    int t = threadIdx.x;
    int c0 = blockIdx.x * 16;
    int a = blockIdx.y;
    int pair = blockIdx.z;
    const float* Wl  = pair ? Wl1  : Wl0;
    const float* Wsk = pair ? Wsk1 : Wsk0;
    float* Wc = pair ? g_Wc1 : g_Wc0;
    int d = t & 127, half = t >> 7;
    float acc[8] = {};
    for (int m0 = 0; m0 < 128; m0 += 64) {
        __syncthreads();
        for (int i = t; i < 64 * 128; i += 256) {
            int mm = i >> 7, dd = i & 127;
            sSk[i] = Wsk[((m0 + mm) * ADIM + a) * 128 + dd];
        }
        for (int i = t; i < 16 * 64; i += 256) {
            int cc = i >> 6, mm = i & 63;
            sWl[i] = Wl[(c0 + cc) * 128 + m0 + mm];
        }
        __syncthreads();
        #pragma unroll 8
        for (int m = 0; m < 64; m++) {
            float sk = sSk[m * 128 + d];
            #pragma unroll
            for (int j = 0; j < 8; j++) {
                int cc = half + 2 * j;
                acc[j] = fmaf(sWl[cc * 64 + m], sk, acc[j]);
            }
        }
    }
    #pragma unroll
    for (int j = 0; j < 8; j++) {
        int c = c0 + half + 2 * j;
        Wc[(a * 256 + c) * 128 + d] = acc[j];
    }
}

// ---------------- edge aggregation: CSR gather into M_s, M_v ----------------
__global__ __launch_bounds__(128) void k_agg(const int* __restrict__ sender,
                                             const float* __restrict__ ea) {
    int n = blockIdx.x;
    int c = threadIdx.x;
    int beg = g_off[n], end = g_off[n + 1];
    float ms1 = 0, ms2 = 0;
    float mv10 = 0, mv11 = 0, mv12 = 0;
    float mv20 = 0, mv21 = 0, mv22 = 0;
    for (int p = beg; p < end; p++) {
        int e = g_csr[p];
        int sj = sender[e];
        float4 y = *(const float4*)&ea[e * 4];
        const float* tw = g_tpw + (size_t)e * 512;
        float ws1 = tw[c], ws2 = tw[128 + c], wv1 = tw[256 + c], wv2 = tw[384 + c];
        float sv = g_s[sj * 128 + c];
        const float* vp = &g_v[sj * 384 + c * 3];
        float v0 = vp[0], v1 = vp[1], v2 = vp[2];
        ms1 = fmaf(ws1 * sv, y.x, ms1);
        float dot = v0 * y.y + v1 * y.z + v2 * y.w;
        ms2 = fmaf(ws2, dot, ms2);
        float a1 = wv1 * sv;
        mv10 = fmaf(a1, y.y, mv10); mv11 = fmaf(a1, y.z, mv11); mv12 = fmaf(a1, y.w, mv12);
        float a2 = wv2 * y.x;
        mv20 = fmaf(a2, v0, mv20); mv21 = fmaf(a2, v1, mv21); mv22 = fmaf(a2, v2, mv22);
    }
    g_Ms[n * 256 + c] = ms1;
    g_Ms[n * 256 + 128 + c] = ms2 * INV_SQRT3;
    float* m1 = &g_Mv[(n * 256 + c) * 3];
    m1[0] = mv10; m1[1] = mv11; m1[2] = mv12;
    float* m2 = &g_Mv[(n * 256 + 128 + c) * 3];
    m2[0] = mv20; m2[1] = mv21; m2[2] = mv22;
}

// ---------------- class-batched output GEMM: out = M @ Wc[a] * OUT_SCALE ----------------
__global__ __launch_bounds__(256) void k_final(float* __restrict__ out) {
    __shared__ float sW[32 * 128];  // 16 KB
    __shared__ float sX[32 * 32];   // 4 KB
    __shared__ int sN[32];
    int t = threadIdx.x;
    int a = blockIdx.z, comp = blockIdx.y;
    int cbeg = g_coff[a], cend = g_coff[a + 1];
    int nt = cend - cbeg;
    int n0 = blockIdx.x * 32;
    if (n0 >= nt) return;
    const float* Wc = (comp == 0) ? g_Wc0 : g_Wc1;
    if (t < 32) {
        int i = n0 + t;
        sN[t] = (i < nt) ? g_clist[cbeg + i] : -1;
    }
    __syncthreads();
    int nb = (t >> 5) << 2, ob = (t & 31) << 2;
    float acc[4][4] = {};
    for (int k0 = 0; k0 < 256; k0 += 32) {
        for (int i = t; i < 32 * 128; i += 256) {
            int kk = i >> 7, dd = i & 127;
            sW[i] = Wc[(a * 256 + k0 + kk) * 128 + dd];
        }
        for (int i = t; i < 32 * 32; i += 256) {
            int r = i >> 5, kk = i & 31;
            int node = sN[r];
            float v = 0.f;
            if (node >= 0) {
                if (comp == 0) v = g_Ms[node * 256 + k0 + kk];
                else           v = g_Mv[(node * 256 + k0 + kk) * 3 + (comp - 1)];
            }
            sX[i] = v;
        }
        __syncthreads();
        #pragma unroll
        for (int kk = 0; kk < 32; kk++) {
            float a0 = sX[(nb + 0) * 32 + kk];
            float a1 = sX[(nb + 1) * 32 + kk];
            float a2 = sX[(nb + 2) * 32 + kk];
            float a3 = sX[(nb + 3) * 32 + kk];
            float4 w = *(const float4*)&sW[kk * 128 + ob];
            acc[0][0] += a0 * w.x; acc[0][1] += a0 * w.y; acc[0][2] += a0 * w.z; acc[0][3] += a0 * w.w;
            acc[1][0] += a1 * w.x; acc[1][1] += a1 * w.y; acc[1][2] += a1 * w.z; acc[1][3] += a1 * w.w;
            acc[2][0] += a2 * w.x; acc[2][1] += a2 * w.y; acc[2][2] += a2 * w.z; acc[2][3] += a2 * w.w;
            acc[3][0] += a3 * w.x; acc[3][1] += a3 * w.y; acc[3][2] += a3 * w.z; acc[3][3] += a3 * w.w;
        }
        __syncthreads();
    }
    #pragma unroll
    for (int r = 0; r < 4; r++) {
        int node = sN[nb + r];
        if (node < 0) continue;
        if (comp == 0) {
            float4 o = make_float4(acc[r][0] * OUT_SCALE, acc[r][1] * OUT_SCALE,
                                   acc[r][2] * OUT_SCALE, acc[r][3] * OUT_SCALE);
            *(float4*)&out[node * 512 + ob] = o;
        } else {
            #pragma unroll
            for (int c = 0; c < 4; c++)
                out[node * 512 + 128 + (ob + c) * 3 + (comp - 1)] = acc[r][c] * OUT_SCALE;
        }
    }
}

// ---------------- launch ----------------
extern "C" void kernel_launch(void* const* d_in, const int* in_sizes, int n_in,
                              void* d_out, int out_size) {
    const float* node_attrs = (const float*)d_in[0];
    const float* node_feats = (const float*)d_in[1];
    const float* edge_attrs = (const float*)d_in[2];
    const float* edge_feats = (const float*)d_in[3];
    const int*   edge_index = (const int*)d_in[4];
    const float* W_up0  = (const float*)d_in[5];
    const float* W_up1  = (const float*)d_in[6];
    const float* W_mlp1 = (const float*)d_in[7];
    const float* W_mlp2 = (const float*)d_in[8];
    const float* W_mlp3 = (const float*)d_in[9];
    const float* W_mlp4 = (const float*)d_in[10];
    const float* W_lin0 = (const float*)d_in[11];
    const float* W_lin1 = (const float*)d_in[12];
    const float* W_skip0 = (const float*)d_in[13];
    const float* W_skip1 = (const float*)d_in[14];
    float* out = (float*)d_out;

    const int* sender = edge_index;            // row 0
    const int* recv   = edge_index + N_EDGES;  // row 1

    cudaFuncSetAttribute(k_tpw, cudaFuncAttributeMaxDynamicSharedMemorySize, TPW_DYN);

    // Launch order: big kernels early so the fixed ncu capture slot (~4th launch)
    // lands on k_tpw instead of plumbing.
    k_w4t<<<128, 256>>>(W_mlp4);                                     // 1
    k_cls<<<(N_NODES + 255) / 256, 256>>>(node_attrs);               // 2
    k_mlp<<<N_EDGES / 128, 128>>>(edge_feats, W_mlp1, W_mlp2, W_mlp3); // 3
    k_tpw<<<N_EDGES / 64, 128, TPW_DYN>>>();                         // 4  (tensor core)
    k_count<<<N_EDGES / 256, 256>>>(recv);                           // 5
    k_sv<<<dim3((N_NODES + 31) / 32, 4), 256>>>(node_feats, W_up0, W_up1); // 6
    k_scan<<<1, 1024>>>();                                           // 7
    k_fill<<<N_EDGES / 256, 256>>>(recv);                            // 8
    k_wc<<<dim3(16, ADIM, 2), 256>>>(W_lin0, W_lin1, W_skip0, W_skip1); // 9
    k_agg<<<N_NODES, 128>>>(sender, edge_attrs);                     // 10
    k_final<<<dim3((N_NODES + 31) / 32, 4, ADIM), 256>>>(out);       // 11
}

// round 11
// speedup vs baseline: 1.1472x; 1.0259x over previous
#include <cuda_runtime.h>
#include <cuda_bf16.h>
#include <cuda_fp16.h>
#include <math.h>

#define N_NODES 10000
#define N_EDGES 160000
#define CDIM 128
#define ADIM 10
#define RDIM 8
#define HDIM 64

#define INV_SQRT_R 0.35355339059327373f
#define INV_SQRT_H 0.125f
#define INV_SQRT_C 0.08838834764831845f
#define INV_SQRT3  0.5773502691896258f
// 1 / (sqrt(2C)*AVG_NEI * sqrt(C*A)) = 1/(256 * sqrt(1280))
#define OUT_SCALE  (1.0f / (256.0f * 35.77708763999664f))

// ---------------- scratch (device globals; no allocations) ----------------
__device__ __nv_bfloat16 g_hhi[N_EDGES * HDIM];       // 20 MB
__device__ __nv_bfloat16 g_hlo[N_EDGES * HDIM];       // 20 MB
__device__ __nv_bfloat16 g_W4T_hi[512 * 64];          // 64 KB (W4 transposed, bf16-hi)
__device__ __nv_bfloat16 g_W4T_lo[512 * 64];          // 64 KB
__device__ __half g_tpw16[(size_t)N_EDGES * 512];     // 163 MB (fp16 tp_w)
__device__ float g_s[N_NODES * CDIM];                 // 5 MB
__device__ float g_v[N_NODES * CDIM * 3];             // 15 MB
__device__ float g_Ms[N_NODES * 256];                 // 10 MB
__device__ float g_Mv[N_NODES * 256 * 3];             // 30 MB
__device__ float g_Wc0[ADIM * 256 * CDIM];            // 1.3 MB
__device__ float g_Wc1[ADIM * 256 * CDIM];            // 1.3 MB
__device__ int   g_cnt[N_NODES];
__device__ int   g_off[N_NODES + 1];
__device__ int   g_cur[N_NODES];
__device__ int   g_csr[N_EDGES];
__device__ int   g_cls[N_NODES];
__device__ int   g_coff[ADIM + 1];
__device__ int   g_ccur[ADIM];
__device__ int   g_clist[N_NODES];

// fast silu: MUFU-based exp + approx divide (rel err ~1e-6, fine vs 1e-3 gate)
__device__ __forceinline__ float silu(float x) {
    float e = __expf(-x);
    return __fdividef(x, 1.0f + e);
}

// ---------------- plumbing ----------------
__global__ void k_cls(const float* __restrict__ na) {
    int n = blockIdx.x * 256 + threadIdx.x;
    if (n >= N_NODES) return;
    g_cnt[n] = 0;
    int a = 0;
    #pragma unroll
    for (int j = 0; j < ADIM; j++)
        if (na[n * ADIM + j] > 0.5f) a = j;
    g_cls[n] = a;
}

__global__ void k_count(const int* __restrict__ recv) {
    int e = blockIdx.x * 256 + threadIdx.x;   // E % 256 == 0
    atomicAdd(&g_cnt[recv[e]], 1);
}

__global__ void k_scan() {
    __shared__ int sp[1024];
    __shared__ int bins[ADIM];
    int t = threadIdx.x;
    if (t < ADIM) bins[t] = 0;
    __syncthreads();
    const int PER = 10;
    int base = t * PER;
    int loc[PER];
    int sum = 0;
    #pragma unroll
    for (int j = 0; j < PER; j++) {
        int idx = base + j;
        int v = 0;
        if (idx < N_NODES) {
            v = g_cnt[idx];
            atomicAdd(&bins[g_cls[idx]], 1);
        }
        loc[j] = sum; sum += v;
    }
    sp[t] = sum;
    __syncthreads();
    for (int d = 1; d < 1024; d <<= 1) {
        int v = (t >= d) ? sp[t - d] : 0;
        __syncthreads();
        sp[t] += v;
        __syncthreads();
    }
    int off = (t > 0) ? sp[t - 1] : 0;
    #pragma unroll
    for (int j = 0; j < PER; j++) {
        int idx = base + j;
        if (idx < N_NODES) { int o = off + loc[j]; g_off[idx] = o; g_cur[idx] = o; }
    }
    if (t == 0) {
        g_off[N_NODES] = sp[1023];
        int s = 0;
        for (int a = 0; a < ADIM; a++) { g_coff[a] = s; g_ccur[a] = s; s += bins[a]; }
        g_coff[ADIM] = s;
    }
}

__global__ void k_fill(const int* __restrict__ recv) {
    int i = blockIdx.x * 256 + threadIdx.x;
    if (i < N_EDGES) {
        int r = recv[i];
        int p = atomicAdd(&g_cur[r], 1);
        g_csr[p] = i;
    }
    if (i < N_NODES) {
        int a = g_cls[i];
        int p = atomicAdd(&g_ccur[a], 1);
        g_clist[p] = i;
    }
}

// ---------------- W4 transpose + bf16 hi/lo split (one-shot tiny kernel) ----------------
__global__ void k_w4t(const float* __restrict__ W4) {
    int gid = blockIdx.x * 256 + threadIdx.x;
    if (gid >= 64 * 512) return;
    int k = gid >> 9, n = gid & 511;
    float v = W4[gid];
    __nv_bfloat16 hi = __float2bfloat16(v);
    float lo = v - __bfloat162float(hi);
    g_W4T_hi[n * 64 + k] = hi;
    g_W4T_lo[n * 64 + k] = __float2bfloat16(lo);
}

// ---------------- edge MLP: 8 -> 64 -> 64 -> 64 (silu) -> bf16 hi/lo split ----------------
__global__ __launch_bounds__(128) void k_mlp(const float* __restrict__ ef,
                                             const float* __restrict__ W1,
                                             const float* __restrict__ W2,
                                             const float* __restrict__ W3) {
    __shared__ float sW1[RDIM * HDIM];
    __shared__ float sW2[HDIM * HDIM];
    __shared__ float sW3[HDIM * HDIM];
    int t = threadIdx.x;
    for (int i = t; i < RDIM * HDIM; i += 128) sW1[i] = W1[i];
    for (int i = t; i < HDIM * HDIM; i += 128) { sW2[i] = W2[i]; sW3[i] = W3[i]; }
    __syncthreads();

    int e = blockIdx.x * 128 + t;              // E % 128 == 0
    float x[RDIM];
    #pragma unroll
    for (int k = 0; k < RDIM; k++) x[k] = ef[e * RDIM + k];

    float h1[HDIM];
    #pragma unroll
    for (int j0 = 0; j0 < HDIM; j0 += 4) {
        float a0 = 0, a1 = 0, a2 = 0, a3 = 0;
        #pragma unroll
        for (int k = 0; k < RDIM; k++) {
            float xv = x[k];
            float4 w = *(const float4*)&sW1[k * HDIM + j0];
            a0 = fmaf(xv, w.x, a0); a1 = fmaf(xv, w.y, a1);
            a2 = fmaf(xv, w.z, a2); a3 = fmaf(xv, w.w, a3);
        }
        h1[j0 + 0] = silu(a0 * INV_SQRT_R);
        h1[j0 + 1] = silu(a1 * INV_SQRT_R);
        h1[j0 + 2] = silu(a2 * INV_SQRT_R);
        h1[j0 + 3] = silu(a3 * INV_SQRT_R);
    }

    float h2[HDIM];
    #pragma unroll
    for (int j0 = 0; j0 < HDIM; j0 += 4) {
        float a0 = 0, a1 = 0, a2 = 0, a3 = 0;
        #pragma unroll
        for (int k = 0; k < HDIM; k++) {
            float hv = h1[k];
            float4 w = *(const float4*)&sW2[k * HDIM + j0];
            a0 = fmaf(hv, w.x, a0); a1 = fmaf(hv, w.y, a1);
            a2 = fmaf(hv, w.z, a2); a3 = fmaf(hv, w.w, a3);
        }
        h2[j0 + 0] = silu(a0 * INV_SQRT_H);
        h2[j0 + 1] = silu(a1 * INV_SQRT_H);
        h2[j0 + 2] = silu(a2 * INV_SQRT_H);
        h2[j0 + 3] = silu(a3 * INV_SQRT_H);
    }

    #pragma unroll
    for (int j0 = 0; j0 < HDIM; j0 += 4) {
        float a0 = 0, a1 = 0, a2 = 0, a3 = 0;
        #pragma unroll
        for (int k = 0; k < HDIM; k++) {
            float hv = h2[k];
            float4 w = *(const float4*)&sW3[k * HDIM + j0];
            a0 = fmaf(hv, w.x, a0); a1 = fmaf(hv, w.y, a1);
            a2 = fmaf(hv, w.z, a2); a3 = fmaf(hv, w.w, a3);
        }
        float o0 = silu(a0 * INV_SQRT_H);
        float o1 = silu(a1 * INV_SQRT_H);
        float o2 = silu(a2 * INV_SQRT_H);
        float o3 = silu(a3 * INV_SQRT_H);
        __nv_bfloat16 hb0 = __float2bfloat16(o0), hb1 = __float2bfloat16(o1);
        __nv_bfloat16 hb2 = __float2bfloat16(o2), hb3 = __float2bfloat16(o3);
        __nv_bfloat16 lb0 = __float2bfloat16(o0 - __bfloat162float(hb0));
        __nv_bfloat16 lb1 = __float2bfloat16(o1 - __bfloat162float(hb1));
        __nv_bfloat16 lb2 = __float2bfloat16(o2 - __bfloat162float(hb2));
        __nv_bfloat16 lb3 = __float2bfloat16(o3 - __bfloat162float(hb3));
        *(__nv_bfloat162*)&g_hhi[e * HDIM + j0]     = __halves2bfloat162(hb0, hb1);
        *(__nv_bfloat162*)&g_hhi[e * HDIM + j0 + 2] = __halves2bfloat162(hb2, hb3);
        *(__nv_bfloat162*)&g_hlo[e * HDIM + j0]     = __halves2bfloat162(lb0, lb1);
        *(__nv_bfloat162*)&g_hlo[e * HDIM + j0 + 2] = __halves2bfloat162(lb2, lb3);
    }
}

// ---------------- tp_w = h @ W4 / sqrt(H) via mma.sync bf16x3 + ldmatrix ----------------
// CTA: 64 edges x 512 outputs (4 chunks of 128). 4 warps: warp tile 32 edges x 64 out.
// D = Ah@Bh + Ah@Bl + Al@Bh, fp32 accumulate, fp16 output.
// Smem rows padded to 72 halves (144 B): ldmatrix rows at 36-word stride -> conflict-free.
#define SAB_HI 0
#define SAB_LO 9216
#define SBB_HI 18432
#define SBB_LO 36864
#define TPW_DYN 55296

__global__ __launch_bounds__(128) void k_tpw() {
    extern __shared__ char sm[];
    unsigned sb;
    asm("{ .reg .u64 t; cvta.to.shared.u64 t, %1; cvt.u32.u64 %0, t; }" : "=r"(sb) : "l"(sm));
    unsigned* smw = (unsigned*)sm;

    int t = threadIdx.x, lane = t & 31, wid = t >> 5;
    int e0 = blockIdx.x * 64;                 // E = 2500 * 64
    const unsigned* hhi = (const unsigned*)g_hhi;
    const unsigned* hlo = (const unsigned*)g_hlo;
    const unsigned* bhi = (const unsigned*)g_W4T_hi;
    const unsigned* blo = (const unsigned*)g_W4T_lo;

    // A fill: 64 rows x 32 words, padded row stride 36 words (144 B)
    for (int i = t; i < 64 * 32; i += 128) {
        int row = i >> 5, k2 = i & 31;
        smw[(SAB_HI >> 2) + row * 36 + k2] = hhi[(e0 + row) * 32 + k2];
        smw[(SAB_LO >> 2) + row * 36 + k2] = hlo[(e0 + row) * 32 + k2];
    }

    int g = lane >> 2, q = lane & 3;
    int m0 = (wid >> 1) * 32;
    int n0 = (wid & 1) * 64;

    // ldmatrix lane offsets (bytes)
    unsigned aoff = (unsigned)((lane & 15) * 144 + ((lane >> 4) << 4)) + m0 * 144;
    unsigned boff = (unsigned)((((lane >> 4) << 3) + (lane & 7)) * 144 + (((lane >> 3) & 1) << 4)) + n0 * 144;

    for (int nh = 0; nh < 4; nh++) {
        __syncthreads();                      // prev readers done (and A fill, iter 0)
        for (int i = t; i < 128 * 32; i += 128) {
            int n = i >> 5, k2 = i & 31;
            smw[(SBB_HI >> 2) + n * 36 + k2] = bhi[(nh * 128 + n) * 32 + k2];
            smw[(SBB_LO >> 2) + n * 36 + k2] = blo[(nh * 128 + n) * 32 + k2];
        }
        __syncthreads();

        float acc[2][8][4];
        #pragma unroll
        for (int mt = 0; mt < 2; mt++)
            #pragma unroll
            for (int nt = 0; nt < 8; nt++)
                #pragma unroll
                for (int j = 0; j < 4; j++) acc[mt][nt][j] = 0.f;

        #pragma unroll
        for (int pass = 0; pass < 3; pass++) {
            unsigned Ab = sb + ((pass == 2) ? SAB_LO : SAB_HI) + aoff;
            unsigned Bb = sb + ((pass == 1) ? SBB_LO : SBB_HI) + boff;
            #pragma unroll
            for (int kt = 0; kt < 4; kt++) {
                unsigned a[2][4];
                #pragma unroll
                for (int mt = 0; mt < 2; mt++) {
                    asm volatile("ldmatrix.sync.aligned.m8n8.x4.shared.b16 {%0,%1,%2,%3}, [%4];"
                        : "=r"(a[mt][0]), "=r"(a[mt][1]), "=r"(a[mt][2]), "=r"(a[mt][3])
                        : "r"(Ab + mt * 2304 + kt * 32));
                }
                #pragma unroll
                for (int j = 0; j < 4; j++) {
                    unsigned b[4];
                    asm volatile("ldmatrix.sync.aligned.m8n8.x4.shared.b16 {%0,%1,%2,%3}, [%4];"
                        : "=r"(b[0]), "=r"(b[1]), "=r"(b[2]), "=r"(b[3])
                        : "r"(Bb + j * 2304 + kt * 32));
                    #pragma unroll
                    for (int h = 0; h < 2; h++) {
                        int nt = j * 2 + h;
                        #pragma unroll
                        for (int mt = 0; mt < 2; mt++) {
                            asm volatile(
                                "mma.sync.aligned.m16n8k16.row.col.f32.bf16.bf16.f32 "
                                "{%0,%1,%2,%3}, {%4,%5,%6,%7}, {%8,%9}, {%0,%1,%2,%3};"
                                : "+f"(acc[mt][nt][0]), "+f"(acc[mt][nt][1]),
                                  "+f"(acc[mt][nt][2]), "+f"(acc[mt][nt][3])
                                : "r"(a[mt][0]), "r"(a[mt][1]), "r"(a[mt][2]), "r"(a[mt][3]),
                                  "r"(b[h * 2]), "r"(b[h * 2 + 1]));
                        }
                    }
                }
            }
        }

        // epilogue: fp16 output. c0,c1 -> (row g, cols q*2..); c2,c3 -> row g+8
        #pragma unroll
        for (int mt = 0; mt < 2; mt++) {
            int er = e0 + m0 + mt * 16 + g;
            #pragma unroll
            for (int nt = 0; nt < 8; nt++) {
                int col = nh * 128 + n0 + nt * 8 + q * 2;
                __half2 d0 = __floats2half2_rn(acc[mt][nt][0] * INV_SQRT_H,
                                               acc[mt][nt][1] * INV_SQRT_H);
                __half2 d1 = __floats2half2_rn(acc[mt][nt][2] * INV_SQRT_H,
                                               acc[mt][nt][3] * INV_SQRT_H);
                *(__half2*)&g_tpw16[(size_t)er * 512 + col]       = d0;
                *(__half2*)&g_tpw16[(size_t)(er + 8) * 512 + col] = d1;
            }
        }
    }
}

// ---------------- node up-projections s, v ----------------
__global__ __launch_bounds__(256) void k_sv(const float* __restrict__ nf,
                                            const float* __restrict__ Wu0,
                                            const float* __restrict__ Wu1) {
    __shared__ float sW[64 * 128];   // 32 KB
    __shared__ float sX[32 * 64];    // 8 KB
    int t = threadIdx.x;
    int comp = blockIdx.y;
    int n0 = blockIdx.x * 32;
    const float* W = (comp == 0) ? Wu0 : Wu1;
    int nb = (t >> 5) << 2, ob = (t & 31) << 2;
    float acc[4][4] = {};
    for (int k0 = 0; k0 < CDIM; k0 += 64) {
        __syncthreads();
        for (int i = t; i < 64 * 128; i += 256) {
            int kk = i >> 7, d = i & 127;
            sW[i] = W[(k0 + kk) * 128 + d];
        }
        for (int i = t; i < 32 * 64; i += 256) {
            int r = i >> 6, kk = i & 63;
            int n = n0 + r;
            float v = 0.f;
            if (n < N_NODES) {
                if (comp == 0) v = nf[n * 512 + k0 + kk];
                else           v = nf[n * 512 + 128 + (k0 + kk) * 3 + (comp - 1)];
            }
            sX[i] = v;
        }
        __syncthreads();
        #pragma unroll
        for (int kk = 0; kk < 64; kk++) {
            float a0 = sX[(nb + 0) * 64 + kk];
            float a1 = sX[(nb + 1) * 64 + kk];
            float a2 = sX[(nb + 2) * 64 + kk];
            float a3 = sX[(nb + 3) * 64 + kk];
            float4 w = *(const float4*)&sW[kk * 128 + ob];
            acc[0][0] += a0 * w.x; acc[0][1] += a0 * w.y; acc[0][2] += a0 * w.z; acc[0][3] += a0 * w.w;
            acc[1][0] += a1 * w.x; acc[1][1] += a1 * w.y; acc[1][2] += a1 * w.z; acc[1][3] += a1 * w.w;
            acc[2][0] += a2 * w.x; acc[2][1] += a2 * w.y; acc[2][2] += a2 * w.z; acc[2][3] += a2 * w.w;
            acc[3][0] += a3 * w.x; acc[3][1] += a3 * w.y; acc[3][2] += a3 * w.z; acc[3][3] += a3 * w.w;
        }
    }
    #pragma unroll
    for (int r = 0; r < 4; r++) {
        int n = n0 + nb + r;
        if (n >= N_NODES) continue;
        if (comp == 0) {
            float4 o = make_float4(acc[r][0] * INV_SQRT_C, acc[r][1] * INV_SQRT_C,
                                   acc[r][2] * INV_SQRT_C, acc[r][3] * INV_SQRT_C);
            *(float4*)&g_s[n * 128 + ob] = o;
        } else {
            #pragma unroll
            for (int c = 0; c < 4; c++)
                g_v[n * 384 + (ob + c) * 3 + (comp - 1)] = acc[r][c] * INV_SQRT_C;
        }
    }
}

// ---------------- fused weights: Wc[a] = W_lin @ W_skip[:, a, :] ----------------
__global__ __launch_bounds__(256) void k_wc(const float* __restrict__ Wl0,
                                            const float* __restrict__ Wl1,
                                            const float* __restrict__ Wsk0,
                                            const float* __restrict__ Wsk1) {
    __shared__ float sSk[64 * 128];  // 32 KB
    __shared__ float sWl[16 * 64];   // 4 KB
    int t = threadIdx.x;
    int c0 = blockIdx.x * 16;
    int a = blockIdx.y;
    int pair = blockIdx.z;
    const float* Wl  = pair ? Wl1  : Wl0;
    const float* Wsk = pair ? Wsk1 : Wsk0;
    float* Wc = pair ? g_Wc1 : g_Wc0;
    int d = t & 127, half = t >> 7;
    float acc[8] = {};
    for (int m0 = 0; m0 < 128; m0 += 64) {
        __syncthreads();
        for (int i = t; i < 64 * 128; i += 256) {
            int mm = i >> 7, dd = i & 127;
            sSk[i] = Wsk[((m0 + mm) * ADIM + a) * 128 + dd];
        }
        for (int i = t; i < 16 * 64; i += 256) {
            int cc = i >> 6, mm = i & 63;
            sWl[i] = Wl[(c0 + cc) * 128 + m0 + mm];
        }
        __syncthreads();
        #pragma unroll 8
        for (int m = 0; m < 64; m++) {
            float sk = sSk[m * 128 + d];
            #pragma unroll
            for (int j = 0; j < 8; j++) {
                int cc = half + 2 * j;
                acc[j] = fmaf(sWl[cc * 64 + m], sk, acc[j]);
            }
        }
    }
    #pragma unroll
    for (int j = 0; j < 8; j++) {
        int c = c0 + half + 2 * j;
        Wc[(a * 256 + c) * 128 + d] = acc[j];
    }
}

// ---------------- edge aggregation: CSR gather into M_s, M_v ----------------
__global__ __launch_bounds__(128) void k_agg(const int* __restrict__ sender,
                                             const float* __restrict__ ea) {
    int n = blockIdx.x;
    int c = threadIdx.x;
    int beg = g_off[n], end = g_off[n + 1];
    float ms1 = 0, ms2 = 0;
    float mv10 = 0, mv11 = 0, mv12 = 0;
    float mv20 = 0, mv21 = 0, mv22 = 0;
    for (int p = beg; p < end; p++) {
        int e = g_csr[p];
        int sj = sender[e];
        float4 y = *(const float4*)&ea[e * 4];
        const __half* tw = g_tpw16 + (size_t)e * 512;
        float ws1 = __half2float(tw[c]);
        float ws2 = __half2float(tw[128 + c]);
        float wv1 = __half2float(tw[256 + c]);
        float wv2 = __half2float(tw[384 + c]);
        float sv = g_s[sj * 128 + c];
        const float* vp = &g_v[sj * 384 + c * 3];
        float v0 = vp[0], v1 = vp[1], v2 = vp[2];
        ms1 = fmaf(ws1 * sv, y.x, ms1);
        float dot = v0 * y.y + v1 * y.z + v2 * y.w;
        ms2 = fmaf(ws2, dot, ms2);
        float a1 = wv1 * sv;
        mv10 = fmaf(a1, y.y, mv10); mv11 = fmaf(a1, y.z, mv11); mv12 = fmaf(a1, y.w, mv12);
        float a2 = wv2 * y.x;
        mv20 = fmaf(a2, v0, mv20); mv21 = fmaf(a2, v1, mv21); mv22 = fmaf(a2, v2, mv22);
    }
    g_Ms[n * 256 + c] = ms1;
    g_Ms[n * 256 + 128 + c] = ms2 * INV_SQRT3;
    float* m1 = &g_Mv[(n * 256 + c) * 3];
    m1[0] = mv10; m1[1] = mv11; m1[2] = mv12;
    float* m2 = &g_Mv[(n * 256 + 128 + c) * 3];
    m2[0] = mv20; m2[1] = mv21; m2[2] = mv22;
}

// ---------------- class-batched output GEMM: out = M @ Wc[a] * OUT_SCALE ----------------
__global__ __launch_bounds__(256) void k_final(float* __restrict__ out) {
    __shared__ float sW[32 * 128];  // 16 KB
    __shared__ float sX[32 * 32];   // 4 KB
    __shared__ int sN[32];
    int t = threadIdx.x;
    int a = blockIdx.z, comp = blockIdx.y;
    int cbeg = g_coff[a], cend = g_coff[a + 1];
    int nt = cend - cbeg;
    int n0 = blockIdx.x * 32;
    if (n0 >= nt) return;
    const float* Wc = (comp == 0) ? g_Wc0 : g_Wc1;
    if (t < 32) {
        int i = n0 + t;
        sN[t] = (i < nt) ? g_clist[cbeg + i] : -1;
    }
    __syncthreads();
    int nb = (t >> 5) << 2, ob = (t & 31) << 2;
    float acc[4][4] = {};
    for (int k0 = 0; k0 < 256; k0 += 32) {
        for (int i = t; i < 32 * 128; i += 256) {
            int kk = i >> 7, dd = i & 127;
            sW[i] = Wc[(a * 256 + k0 + kk) * 128 + dd];
        }
        for (int i = t; i < 32 * 32; i += 256) {
            int r = i >> 5, kk = i & 31;
            int node = sN[r];
            float v = 0.f;
            if (node >= 0) {
                if (comp == 0) v = g_Ms[node * 256 + k0 + kk];
                else           v = g_Mv[(node * 256 + k0 + kk) * 3 + (comp - 1)];
            }
            sX[i] = v;
        }
        __syncthreads();
        #pragma unroll
        for (int kk = 0; kk < 32; kk++) {
            float a0 = sX[(nb + 0) * 32 + kk];
            float a1 = sX[(nb + 1) * 32 + kk];
            float a2 = sX[(nb + 2) * 32 + kk];
            float a3 = sX[(nb + 3) * 32 + kk];
            float4 w = *(const float4*)&sW[kk * 128 + ob];
            acc[0][0] += a0 * w.x; acc[0][1] += a0 * w.y; acc[0][2] += a0 * w.z; acc[0][3] += a0 * w.w;
            acc[1][0] += a1 * w.x; acc[1][1] += a1 * w.y; acc[1][2] += a1 * w.z; acc[1][3] += a1 * w.w;
            acc[2][0] += a2 * w.x; acc[2][1] += a2 * w.y; acc[2][2] += a2 * w.z; acc[2][3] += a2 * w.w;
            acc[3][0] += a3 * w.x; acc[3][1] += a3 * w.y; acc[3][2] += a3 * w.z; acc[3][3] += a3 * w.w;
        }
        __syncthreads();
    }
    #pragma unroll
    for (int r = 0; r < 4; r++) {
        int node = sN[nb + r];
        if (node < 0) continue;
        if (comp == 0) {
            float4 o = make_float4(acc[r][0] * OUT_SCALE, acc[r][1] * OUT_SCALE,
                                   acc[r][2] * OUT_SCALE, acc[r][3] * OUT_SCALE);
            *(float4*)&out[node * 512 + ob] = o;
        } else {
            #pragma unroll
            for (int c = 0; c < 4; c++)
                out[node * 512 + 128 + (ob + c) * 3 + (comp - 1)] = acc[r][c] * OUT_SCALE;
        }
    }
}

// ---------------- launch ----------------
extern "C" void kernel_launch(void* const* d_in, const int* in_sizes, int n_in,
                              void* d_out, int out_size) {
    const float* node_attrs = (const float*)d_in[0];
    const float* node_feats = (const float*)d_in[1];
    const float* edge_attrs = (const float*)d_in[2];
    const float* edge_feats = (const float*)d_in[3];
    const int*   edge_index = (const int*)d_in[4];
    const float* W_up0  = (const float*)d_in[5];
    const float* W_up1  = (const float*)d_in[6];
    const float* W_mlp1 = (const float*)d_in[7];
    const float* W_mlp2 = (const float*)d_in[8];
    const float* W_mlp3 = (const float*)d_in[9];
    const float* W_mlp4 = (const float*)d_in[10];
    const float* W_lin0 = (const float*)d_in[11];
    const float* W_lin1 = (const float*)d_in[12];
    const float* W_skip0 = (const float*)d_in[13];
    const float* W_skip1 = (const float*)d_in[14];
    float* out = (float*)d_out;

    const int* sender = edge_index;            // row 0
    const int* recv   = edge_index + N_EDGES;  // row 1

    cudaFuncSetAttribute(k_tpw, cudaFuncAttributeMaxDynamicSharedMemorySize, TPW_DYN);

    // Launch order: k_tpw kept at slot 4 (ncu capture slot).
    k_w4t<<<128, 256>>>(W_mlp4);                                     // 1
    k_cls<<<(N_NODES + 255) / 256, 256>>>(node_attrs);               // 2
    k_mlp<<<N_EDGES / 128, 128>>>(edge_feats, W_mlp1, W_mlp2, W_mlp3); // 3
    k_tpw<<<N_EDGES / 64, 128, TPW_DYN>>>();                         // 4  (tensor core)
    k_count<<<N_EDGES / 256, 256>>>(recv);                           // 5
    k_sv<<<dim3((N_NODES + 31) / 32, 4), 256>>>(node_feats, W_up0, W_up1); // 6
    k_scan<<<1, 1024>>>();                                           // 7
    k_fill<<<N_EDGES / 256, 256>>>(recv);                            // 8
    k_wc<<<dim3(16, ADIM, 2), 256>>>(W_lin0, W_lin1, W_skip0, W_skip1); // 9
    k_agg<<<N_NODES, 128>>>(sender, edge_attrs);                     // 10
    k_final<<<dim3((N_NODES + 31) / 32, 4, ADIM), 256>>>(out);       // 11
}

// round 12
// speedup vs baseline: 1.3626x; 1.1878x over previous
#include <cuda_runtime.h>
#include <cuda_bf16.h>
#include <cuda_fp16.h>
#include <math.h>

#define N_NODES 10000
#define N_EDGES 160000
#define CDIM 128
#define ADIM 10
#define RDIM 8
#define HDIM 64

#define INV_SQRT_R 0.35355339059327373f
#define INV_SQRT_H 0.125f
#define INV_SQRT_C 0.08838834764831845f
#define INV_SQRT3  0.5773502691896258f
// 1 / (sqrt(2C)*AVG_NEI * sqrt(C*A)) = 1/(256 * sqrt(1280))
#define OUT_SCALE  (1.0f / (256.0f * 35.77708763999664f))

// ---------------- scratch (device globals; no allocations) ----------------
__device__ __half g_h16[N_EDGES * HDIM];              // 20 MB (fp16 edge MLP out)
__device__ __half g_W4T16[512 * 64];                  // 64 KB (W4 transposed, fp16)
__device__ __half g_tpw16[(size_t)N_EDGES * 512];     // 163 MB (fp16 tp_w)
__device__ float g_s[N_NODES * CDIM];                 // 5 MB
__device__ float g_v[N_NODES * CDIM * 3];             // 15 MB
__device__ float g_Ms[N_NODES * 256];                 // 10 MB
__device__ float g_Mv[N_NODES * 256 * 3];             // 30 MB
__device__ float g_Wc0[ADIM * 256 * CDIM];            // 1.3 MB
__device__ float g_Wc1[ADIM * 256 * CDIM];            // 1.3 MB
__device__ int   g_cnt[N_NODES];
__device__ int   g_off[N_NODES + 1];
__device__ int   g_cur[N_NODES];
__device__ int   g_csr[N_EDGES];
__device__ int   g_cls[N_NODES];
__device__ int   g_coff[ADIM + 1];
__device__ int   g_ccur[ADIM];
__device__ int   g_clist[N_NODES];

// fast silu: MUFU-based exp + approx divide (rel err ~1e-6, fine vs 1e-3 gate)
__device__ __forceinline__ float silu(float x) {
    float e = __expf(-x);
    return __fdividef(x, 1.0f + e);
}

// ---------------- plumbing ----------------
__global__ void k_cls(const float* __restrict__ na) {
    int n = blockIdx.x * 256 + threadIdx.x;
    if (n >= N_NODES) return;
    g_cnt[n] = 0;
    int a = 0;
    #pragma unroll
    for (int j = 0; j < ADIM; j++)
        if (na[n * ADIM + j] > 0.5f) a = j;
    g_cls[n] = a;
}

__global__ void k_count(const int* __restrict__ recv) {
    int e = blockIdx.x * 256 + threadIdx.x;   // E % 256 == 0
    atomicAdd(&g_cnt[recv[e]], 1);
}

__global__ void k_scan() {
    __shared__ int sp[1024];
    __shared__ int bins[ADIM];
    int t = threadIdx.x;
    if (t < ADIM) bins[t] = 0;
    __syncthreads();
    const int PER = 10;
    int base = t * PER;
    int loc[PER];
    int sum = 0;
    #pragma unroll
    for (int j = 0; j < PER; j++) {
        int idx = base + j;
        int v = 0;
        if (idx < N_NODES) {
            v = g_cnt[idx];
            atomicAdd(&bins[g_cls[idx]], 1);
        }
        loc[j] = sum; sum += v;
    }
    sp[t] = sum;
    __syncthreads();
    for (int d = 1; d < 1024; d <<= 1) {
        int v = (t >= d) ? sp[t - d] : 0;
        __syncthreads();
        sp[t] += v;
        __syncthreads();
    }
    int off = (t > 0) ? sp[t - 1] : 0;
    #pragma unroll
    for (int j = 0; j < PER; j++) {
        int idx = base + j;
        if (idx < N_NODES) { int o = off + loc[j]; g_off[idx] = o; g_cur[idx] = o; }
    }
    if (t == 0) {
        g_off[N_NODES] = sp[1023];
        int s = 0;
        for (int a = 0; a < ADIM; a++) { g_coff[a] = s; g_ccur[a] = s; s += bins[a]; }
        g_coff[ADIM] = s;
    }
}

__global__ void k_fill(const int* __restrict__ recv) {
    int i = blockIdx.x * 256 + threadIdx.x;
    if (i < N_EDGES) {
        int r = recv[i];
        int p = atomicAdd(&g_cur[r], 1);
        g_csr[p] = i;
    }
    if (i < N_NODES) {
        int a = g_cls[i];
        int p = atomicAdd(&g_ccur[a], 1);
        g_clist[p] = i;
    }
}

// ---------------- W4 transpose to fp16 (one-shot tiny kernel) ----------------
__global__ void k_w4t(const float* __restrict__ W4) {
    int gid = blockIdx.x * 256 + threadIdx.x;
    if (gid >= 64 * 512) return;
    int k = gid >> 9, n = gid & 511;
    g_W4T16[n * 64 + k] = __float2half_rn(W4[gid]);
}

// ---------------- edge MLP: 8 -> 64 -> 64 -> 64 (silu) -> fp16 ----------------
__global__ __launch_bounds__(128) void k_mlp(const float* __restrict__ ef,
                                             const float* __restrict__ W1,
                                             const float* __restrict__ W2,
                                             const float* __restrict__ W3) {
    __shared__ float sW1[RDIM * HDIM];
    __shared__ float sW2[HDIM * HDIM];
    __shared__ float sW3[HDIM * HDIM];
    int t = threadIdx.x;
    for (int i = t; i < RDIM * HDIM; i += 128) sW1[i] = W1[i];
    for (int i = t; i < HDIM * HDIM; i += 128) { sW2[i] = W2[i]; sW3[i] = W3[i]; }
    __syncthreads();

    int e = blockIdx.x * 128 + t;              // E % 128 == 0
    float x[RDIM];
    #pragma unroll
    for (int k = 0; k < RDIM; k++) x[k] = ef[e * RDIM + k];

    float h1[HDIM];
    #pragma unroll
    for (int j0 = 0; j0 < HDIM; j0 += 4) {
        float a0 = 0, a1 = 0, a2 = 0, a3 = 0;
        #pragma unroll
        for (int k = 0; k < RDIM; k++) {
            float xv = x[k];
            float4 w = *(const float4*)&sW1[k * HDIM + j0];
            a0 = fmaf(xv, w.x, a0); a1 = fmaf(xv, w.y, a1);
            a2 = fmaf(xv, w.z, a2); a3 = fmaf(xv, w.w, a3);
        }
        h1[j0 + 0] = silu(a0 * INV_SQRT_R);
        h1[j0 + 1] = silu(a1 * INV_SQRT_R);
        h1[j0 + 2] = silu(a2 * INV_SQRT_R);
        h1[j0 + 3] = silu(a3 * INV_SQRT_R);
    }

    float h2[HDIM];
    #pragma unroll
    for (int j0 = 0; j0 < HDIM; j0 += 4) {
        float a0 = 0, a1 = 0, a2 = 0, a3 = 0;
        #pragma unroll
        for (int k = 0; k < HDIM; k++) {
            float hv = h1[k];
            float4 w = *(const float4*)&sW2[k * HDIM + j0];
            a0 = fmaf(hv, w.x, a0); a1 = fmaf(hv, w.y, a1);
            a2 = fmaf(hv, w.z, a2); a3 = fmaf(hv, w.w, a3);
        }
        h2[j0 + 0] = silu(a0 * INV_SQRT_H);
        h2[j0 + 1] = silu(a1 * INV_SQRT_H);
        h2[j0 + 2] = silu(a2 * INV_SQRT_H);
        h2[j0 + 3] = silu(a3 * INV_SQRT_H);
    }

    #pragma unroll
    for (int j0 = 0; j0 < HDIM; j0 += 4) {
        float a0 = 0, a1 = 0, a2 = 0, a3 = 0;
        #pragma unroll
        for (int k = 0; k < HDIM; k++) {
            float hv = h2[k];
            float4 w = *(const float4*)&sW3[k * HDIM + j0];
            a0 = fmaf(hv, w.x, a0); a1 = fmaf(hv, w.y, a1);
            a2 = fmaf(hv, w.z, a2); a3 = fmaf(hv, w.w, a3);
        }
        __half2 p0 = __floats2half2_rn(silu(a0 * INV_SQRT_H), silu(a1 * INV_SQRT_H));
        __half2 p1 = __floats2half2_rn(silu(a2 * INV_SQRT_H), silu(a3 * INV_SQRT_H));
        *(__half2*)&g_h16[e * HDIM + j0]     = p0;
        *(__half2*)&g_h16[e * HDIM + j0 + 2] = p1;
    }
}

// ---------------- tp_w = h @ W4 / sqrt(H) via single-pass fp16 mma.sync ----------------
// CTA: 64 edges x 512 outputs (4 chunks of 128). 4 warps: warp tile 32 edges x 64 out.
// fp16 inputs, fp32 accumulate, fp16 output.
// Smem rows padded to 72 halves (144 B): ldmatrix conflict-free.
#define SAB 0
#define SBB 9216
#define TPW_DYN 27648

__global__ __launch_bounds__(128) void k_tpw() {
    extern __shared__ char sm[];
    unsigned sb;
    asm("{ .reg .u64 t; cvta.to.shared.u64 t, %1; cvt.u32.u64 %0, t; }" : "=r"(sb) : "l"(sm));
    unsigned* smw = (unsigned*)sm;

    int t = threadIdx.x, lane = t & 31, wid = t >> 5;
    int e0 = blockIdx.x * 64;                 // E = 2500 * 64
    const unsigned* hh = (const unsigned*)g_h16;
    const unsigned* bb = (const unsigned*)g_W4T16;

    // A fill: 64 rows x 32 words, padded row stride 36 words (144 B)
    for (int i = t; i < 64 * 32; i += 128) {
        int row = i >> 5, k2 = i & 31;
        smw[(SAB >> 2) + row * 36 + k2] = hh[(e0 + row) * 32 + k2];
    }

    int g = lane >> 2, q = lane & 3;
    int m0 = (wid >> 1) * 32;
    int n0 = (wid & 1) * 64;

    // ldmatrix lane offsets (bytes), layout identical to verified R11 version
    unsigned aoff = (unsigned)((lane & 15) * 144 + ((lane >> 4) << 4)) + m0 * 144;
    unsigned boff = (unsigned)((((lane >> 4) << 3) + (lane & 7)) * 144 + (((lane >> 3) & 1) << 4)) + n0 * 144;
    unsigned Ab = sb + SAB + aoff;
    unsigned Bb = sb + SBB + boff;

    for (int nh = 0; nh < 4; nh++) {
        __syncthreads();                      // prev readers done (and A fill, iter 0)
        for (int i = t; i < 128 * 32; i += 128) {
            int n = i >> 5, k2 = i & 31;
            smw[(SBB >> 2) + n * 36 + k2] = bb[(nh * 128 + n) * 32 + k2];
        }
        __syncthreads();

        float acc[2][8][4];
        #pragma unroll
        for (int mt = 0; mt < 2; mt++)
            #pragma unroll
            for (int nt = 0; nt < 8; nt++)
                #pragma unroll
                for (int j = 0; j < 4; j++) acc[mt][nt][j] = 0.f;

        #pragma unroll
        for (int kt = 0; kt < 4; kt++) {
            unsigned a[2][4];
            #pragma unroll
            for (int mt = 0; mt < 2; mt++) {
                asm volatile("ldmatrix.sync.aligned.m8n8.x4.shared.b16 {%0,%1,%2,%3}, [%4];"
                    : "=r"(a[mt][0]), "=r"(a[mt][1]), "=r"(a[mt][2]), "=r"(a[mt][3])
                    : "r"(Ab + mt * 2304 + kt * 32));
            }
            #pragma unroll
            for (int j = 0; j < 4; j++) {
                unsigned b[4];
                asm volatile("ldmatrix.sync.aligned.m8n8.x4.shared.b16 {%0,%1,%2,%3}, [%4];"
                    : "=r"(b[0]), "=r"(b[1]), "=r"(b[2]), "=r"(b[3])
                    : "r"(Bb + j * 2304 + kt * 32));
                #pragma unroll
                for (int h = 0; h < 2; h++) {
                    int nt = j * 2 + h;
                    #pragma unroll
                    for (int mt = 0; mt < 2; mt++) {
                        asm volatile(
                            "mma.sync.aligned.m16n8k16.row.col.f32.f16.f16.f32 "
                            "{%0,%1,%2,%3}, {%4,%5,%6,%7}, {%8,%9}, {%0,%1,%2,%3};"
                            : "+f"(acc[mt][nt][0]), "+f"(acc[mt][nt][1]),
                              "+f"(acc[mt][nt][2]), "+f"(acc[mt][nt][3])
                            : "r"(a[mt][0]), "r"(a[mt][1]), "r"(a[mt][2]), "r"(a[mt][3]),
                              "r"(b[h * 2]), "r"(b[h * 2 + 1]));
                    }
                }
            }
        }

        // epilogue: fp16 output. c0,c1 -> (row g, cols q*2..); c2,c3 -> row g+8
        #pragma unroll
        for (int mt = 0; mt < 2; mt++) {
            int er = e0 + m0 + mt * 16 + g;
            #pragma unroll
            for (int nt = 0; nt < 8; nt++) {
                int col = nh * 128 + n0 + nt * 8 + q * 2;
                __half2 d0 = __floats2half2_rn(acc[mt][nt][0] * INV_SQRT_H,
                                               acc[mt][nt][1] * INV_SQRT_H);
                __half2 d1 = __floats2half2_rn(acc[mt][nt][2] * INV_SQRT_H,
                                               acc[mt][nt][3] * INV_SQRT_H);
                *(__half2*)&g_tpw16[(size_t)er * 512 + col]       = d0;
                *(__half2*)&g_tpw16[(size_t)(er + 8) * 512 + col] = d1;
            }
        }
    }
}

// ---------------- node up-projections s, v ----------------
__global__ __launch_bounds__(256) void k_sv(const float* __restrict__ nf,
                                            const float* __restrict__ Wu0,
                                            const float* __restrict__ Wu1) {
    __shared__ float sW[64 * 128];   // 32 KB
    __shared__ float sX[32 * 64];    // 8 KB
    int t = threadIdx.x;
    int comp = blockIdx.y;
    int n0 = blockIdx.x * 32;
    const float* W = (comp == 0) ? Wu0 : Wu1;
    int nb = (t >> 5) << 2, ob = (t & 31) << 2;
    float acc[4][4] = {};
    for (int k0 = 0; k0 < CDIM; k0 += 64) {
        __syncthreads();
        for (int i = t; i < 64 * 128; i += 256) {
            int kk = i >> 7, d = i & 127;
            sW[i] = W[(k0 + kk) * 128 + d];
        }
        for (int i = t; i < 32 * 64; i += 256) {
            int r = i >> 6, kk = i & 63;
            int n = n0 + r;
            float v = 0.f;
            if (n < N_NODES) {
                if (comp == 0) v = nf[n * 512 + k0 + kk];
                else           v = nf[n * 512 + 128 + (k0 + kk) * 3 + (comp - 1)];
            }
            sX[i] = v;
        }
        __syncthreads();
        #pragma unroll
        for (int kk = 0; kk < 64; kk++) {
            float a0 = sX[(nb + 0) * 64 + kk];
            float a1 = sX[(nb + 1) * 64 + kk];
            float a2 = sX[(nb + 2) * 64 + kk];
            float a3 = sX[(nb + 3) * 64 + kk];
            float4 w = *(const float4*)&sW[kk * 128 + ob];
            acc[0][0] += a0 * w.x; acc[0][1] += a0 * w.y; acc[0][2] += a0 * w.z; acc[0][3] += a0 * w.w;
            acc[1][0] += a1 * w.x; acc[1][1] += a1 * w.y; acc[1][2] += a1 * w.z; acc[1][3] += a1 * w.w;
            acc[2][0] += a2 * w.x; acc[2][1] += a2 * w.y; acc[2][2] += a2 * w.z; acc[2][3] += a2 * w.w;
            acc[3][0] += a3 * w.x; acc[3][1] += a3 * w.y; acc[3][2] += a3 * w.z; acc[3][3] += a3 * w.w;
        }
    }
    #pragma unroll
    for (int r = 0; r < 4; r++) {
        int n = n0 + nb + r;
        if (n >= N_NODES) continue;
        if (comp == 0) {
            float4 o = make_float4(acc[r][0] * INV_SQRT_C, acc[r][1] * INV_SQRT_C,
                                   acc[r][2] * INV_SQRT_C, acc[r][3] * INV_SQRT_C);
            *(float4*)&g_s[n * 128 + ob] = o;
        } else {
            #pragma unroll
            for (int c = 0; c < 4; c++)
                g_v[n * 384 + (ob + c) * 3 + (comp - 1)] = acc[r][c] * INV_SQRT_C;
        }
    }
}

// ---------------- fused weights: Wc[a] = W_lin @ W_skip[:, a, :] ----------------
__global__ __launch_bounds__(256) void k_wc(const float* __restrict__ Wl0,
                                            const float* __restrict__ Wl1,
                                            const float* __restrict__ Wsk0,
                                            const float* __restrict__ Wsk1) {
    __shared__ float sSk[64 * 128];  // 32 KB
    __shared__ float sWl[16 * 64];   // 4 KB
    int t = threadIdx.x;
    int c0 = blockIdx.x * 16;
    int a = blockIdx.y;
    int pair = blockIdx.z;
    const float* Wl  = pair ? Wl1  : Wl0;
    const float* Wsk = pair ? Wsk1 : Wsk0;
    float* Wc = pair ? g_Wc1 : g_Wc0;
    int d = t & 127, half = t >> 7;
    float acc[8] = {};
    for (int m0 = 0; m0 < 128; m0 += 64) {
        __syncthreads();
        for (int i = t; i < 64 * 128; i += 256) {
            int mm = i >> 7, dd = i & 127;
            sSk[i] = Wsk[((m0 + mm) * ADIM + a) * 128 + dd];
        }
        for (int i = t; i < 16 * 64; i += 256) {
            int cc = i >> 6, mm = i & 63;
            sWl[i] = Wl[(c0 + cc) * 128 + m0 + mm];
        }
        __syncthreads();
        #pragma unroll 8
        for (int m = 0; m < 64; m++) {
            float sk = sSk[m * 128 + d];
            #pragma unroll
            for (int j = 0; j < 8; j++) {
                int cc = half + 2 * j;
                acc[j] = fmaf(sWl[cc * 64 + m], sk, acc[j]);
            }
        }
    }
    #pragma unroll
    for (int j = 0; j < 8; j++) {
        int c = c0 + half + 2 * j;
        Wc[(a * 256 + c) * 128 + d] = acc[j];
    }
}

// ---------------- edge aggregation: CSR gather into M_s, M_v ----------------
__global__ __launch_bounds__(128) void k_agg(const int* __restrict__ sender,
                                             const float* __restrict__ ea) {
    int n = blockIdx.x;
    int c = threadIdx.x;
    int beg = g_off[n], end = g_off[n + 1];
    float ms1 = 0, ms2 = 0;
    float mv10 = 0, mv11 = 0, mv12 = 0;
    float mv20 = 0, mv21 = 0, mv22 = 0;
    for (int p = beg; p < end; p++) {
        int e = g_csr[p];
        int sj = sender[e];
        float4 y = *(const float4*)&ea[e * 4];
        const __half* tw = g_tpw16 + (size_t)e * 512;
        float ws1 = __half2float(tw[c]);
        float ws2 = __half2float(tw[128 + c]);
        float wv1 = __half2float(tw[256 + c]);
        float wv2 = __half2float(tw[384 + c]);
        float sv = g_s[sj * 128 + c];
        const float* vp = &g_v[sj * 384 + c * 3];
        float v0 = vp[0], v1 = vp[1], v2 = vp[2];
        ms1 = fmaf(ws1 * sv, y.x, ms1);
        float dot = v0 * y.y + v1 * y.z + v2 * y.w;
        ms2 = fmaf(ws2, dot, ms2);
        float a1 = wv1 * sv;
        mv10 = fmaf(a1, y.y, mv10); mv11 = fmaf(a1, y.z, mv11); mv12 = fmaf(a1, y.w, mv12);
        float a2 = wv2 * y.x;
        mv20 = fmaf(a2, v0, mv20); mv21 = fmaf(a2, v1, mv21); mv22 = fmaf(a2, v2, mv22);
    }
    g_Ms[n * 256 + c] = ms1;
    g_Ms[n * 256 + 128 + c] = ms2 * INV_SQRT3;
    float* m1 = &g_Mv[(n * 256 + c) * 3];
    m1[0] = mv10; m1[1] = mv11; m1[2] = mv12;
    float* m2 = &g_Mv[(n * 256 + 128 + c) * 3];
    m2[0] = mv20; m2[1] = mv21; m2[2] = mv22;
}

// ---------------- class-batched output GEMM: out = M @ Wc[a] * OUT_SCALE ----------------
__global__ __launch_bounds__(256) void k_final(float* __restrict__ out) {
    __shared__ float sW[32 * 128];  // 16 KB
    __shared__ float sX[32 * 32];   // 4 KB
    __shared__ int sN[32];
    int t = threadIdx.x;
    int a = blockIdx.z, comp = blockIdx.y;
    int cbeg = g_coff[a], cend = g_coff[a + 1];
    int nt = cend - cbeg;
    int n0 = blockIdx.x * 32;
    if (n0 >= nt) return;
    const float* Wc = (comp == 0) ? g_Wc0 : g_Wc1;
    if (t < 32) {
        int i = n0 + t;
        sN[t] = (i < nt) ? g_clist[cbeg + i] : -1;
    }
    __syncthreads();
    int nb = (t >> 5) << 2, ob = (t & 31) << 2;
    float acc[4][4] = {};
    for (int k0 = 0; k0 < 256; k0 += 32) {
        for (int i = t; i < 32 * 128; i += 256) {
            int kk = i >> 7, dd = i & 127;
            sW[i] = Wc[(a * 256 + k0 + kk) * 128 + dd];
        }
        for (int i = t; i < 32 * 32; i += 256) {
            int r = i >> 5, kk = i & 31;
            int node = sN[r];
            float v = 0.f;
            if (node >= 0) {
                if (comp == 0) v = g_Ms[node * 256 + k0 + kk];
                else           v = g_Mv[(node * 256 + k0 + kk) * 3 + (comp - 1)];
            }
            sX[i] = v;
        }
        __syncthreads();
        #pragma unroll
        for (int kk = 0; kk < 32; kk++) {
            float a0 = sX[(nb + 0) * 32 + kk];
            float a1 = sX[(nb + 1) * 32 + kk];
            float a2 = sX[(nb + 2) * 32 + kk];
            float a3 = sX[(nb + 3) * 32 + kk];
            float4 w = *(const float4*)&sW[kk * 128 + ob];
            acc[0][0] += a0 * w.x; acc[0][1] += a0 * w.y; acc[0][2] += a0 * w.z; acc[0][3] += a0 * w.w;
            acc[1][0] += a1 * w.x; acc[1][1] += a1 * w.y; acc[1][2] += a1 * w.z; acc[1][3] += a1 * w.w;
            acc[2][0] += a2 * w.x; acc[2][1] += a2 * w.y; acc[2][2] += a2 * w.z; acc[2][3] += a2 * w.w;
            acc[3][0] += a3 * w.x; acc[3][1] += a3 * w.y; acc[3][2] += a3 * w.z; acc[3][3] += a3 * w.w;
        }
        __syncthreads();
    }
    #pragma unroll
    for (int r = 0; r < 4; r++) {
        int node = sN[nb + r];
        if (node < 0) continue;
        if (comp == 0) {
            float4 o = make_float4(acc[r][0] * OUT_SCALE, acc[r][1] * OUT_SCALE,
                                   acc[r][2] * OUT_SCALE, acc[r][3] * OUT_SCALE);
            *(float4*)&out[node * 512 + ob] = o;
        } else {
            #pragma unroll
            for (int c = 0; c < 4; c++)
                out[node * 512 + 128 + (ob + c) * 3 + (comp - 1)] = acc[r][c] * OUT_SCALE;
        }
    }
}

// ---------------- launch ----------------
extern "C" void kernel_launch(void* const* d_in, const int* in_sizes, int n_in,
                              void* d_out, int out_size) {
    const float* node_attrs = (const float*)d_in[0];
    const float* node_feats = (const float*)d_in[1];
    const float* edge_attrs = (const float*)d_in[2];
    const float* edge_feats = (const float*)d_in[3];
    const int*   edge_index = (const int*)d_in[4];
    const float* W_up0  = (const float*)d_in[5];
    const float* W_up1  = (const float*)d_in[6];
    const float* W_mlp1 = (const float*)d_in[7];
    const float* W_mlp2 = (const float*)d_in[8];
    const float* W_mlp3 = (const float*)d_in[9];
    const float* W_mlp4 = (const float*)d_in[10];
    const float* W_lin0 = (const float*)d_in[11];
    const float* W_lin1 = (const float*)d_in[12];
    const float* W_skip0 = (const float*)d_in[13];
    const float* W_skip1 = (const float*)d_in[14];
    float* out = (float*)d_out;

    const int* sender = edge_index;            // row 0
    const int* recv   = edge_index + N_EDGES;  // row 1

    cudaFuncSetAttribute(k_tpw, cudaFuncAttributeMaxDynamicSharedMemorySize, TPW_DYN);

    // Launch order: k_tpw kept at slot 4 (ncu capture slot).
    k_w4t<<<128, 256>>>(W_mlp4);                                     // 1
    k_cls<<<(N_NODES + 255) / 256, 256>>>(node_attrs);               // 2
    k_mlp<<<N_EDGES / 128, 128>>>(edge_feats, W_mlp1, W_mlp2, W_mlp3); // 3
    k_tpw<<<N_EDGES / 64, 128, TPW_DYN>>>();                         // 4  (tensor core)
    k_count<<<N_EDGES / 256, 256>>>(recv);                           // 5
    k_sv<<<dim3((N_NODES + 31) / 32, 4), 256>>>(node_feats, W_up0, W_up1); // 6
    k_scan<<<1, 1024>>>();                                           // 7
    k_fill<<<N_EDGES / 256, 256>>>(recv);                            // 8
    k_wc<<<dim3(16, ADIM, 2), 256>>>(W_lin0, W_lin1, W_skip0, W_skip1); // 9
    k_agg<<<N_NODES, 128>>>(sender, edge_attrs);                     // 10
    k_final<<<dim3((N_NODES + 31) / 32, 4, ADIM), 256>>>(out);       // 11
}

// round 14
// speedup vs baseline: 1.6946x; 1.2436x over previous
#include <cuda_runtime.h>
#include <cuda_fp16.h>
#include <math.h>

#define N_NODES 10000
#define N_EDGES 160000
#define CDIM 128
#define ADIM 10
#define RDIM 8
#define HDIM 64
#define NPAD 10688

#define INV_SQRT_R 0.35355339059327373f
#define INV_SQRT_H 0.125f
#define INV_SQRT_C 0.08838834764831845f
#define INV_SQRT3  0.5773502691896258f
// 1 / (sqrt(2C)*AVG_NEI * sqrt(C*A)) = 1/(256 * sqrt(1280))
#define OUT_SCALE  (1.0f / (256.0f * 35.77708763999664f))

// ---------------- scratch (device globals; no allocations) ----------------
__device__ __half g_h16[N_EDGES * HDIM];              // 20 MB (fp16 edge MLP out)
__device__ __half g_W4T16[512 * 64];                  // 64 KB (W4 transposed, fp16)
__device__ __half g_tpw16[(size_t)N_EDGES * 512];     // 163 MB (fp16 tp_w)
__device__ float g_s[N_NODES * CDIM];                 // 5 MB
__device__ float g_v[N_NODES * CDIM * 3];             // 15 MB
__device__ __half g_M16[4 * N_NODES * 256];           // 20 MB (fp16 M planes)
__device__ __half g_WcT0[ADIM * 128 * 256];           // 640 KB (fused W, transposed fp16)
__device__ __half g_WcT1[ADIM * 128 * 256];           // 640 KB
__device__ int   g_cnt[N_NODES];
__device__ int   g_off[N_NODES + 1];
__device__ int   g_cur[N_NODES];
__device__ int   g_csr[N_EDGES];
__device__ int   g_cls[N_NODES];
__device__ int   g_pcoff[ADIM + 1];
__device__ int   g_ccur[ADIM];
__device__ int   g_clistp[NPAD];

// fast silu: MUFU-based exp + approx divide (rel err ~1e-6, fine vs 1e-3 gate)
__device__ __forceinline__ float silu(float x) {
    float e = __expf(-x);
    return __fdividef(x, 1.0f + e);
}

__device__ __forceinline__ unsigned smem_u32(const void* p) {
    unsigned a;
    asm("{ .reg .u64 t; cvta.to.shared.u64 t, %1; cvt.u32.u64 %0, t; }" : "=r"(a) : "l"(p));
    return a;
}

// ---------------- plumbing ----------------
__global__ void k_cls(const float* __restrict__ na) {
    int n = blockIdx.x * 256 + threadIdx.x;
    if (n < NPAD) g_clistp[n] = -1;
    if (n >= N_NODES) return;
    g_cnt[n] = 0;
    int a = 0;
    #pragma unroll
    for (int j = 0; j < ADIM; j++)
        if (na[n * ADIM + j] > 0.5f) a = j;
    g_cls[n] = a;
}

__global__ void k_count(const int* __restrict__ recv) {
    int e = blockIdx.x * 256 + threadIdx.x;   // E % 256 == 0
    atomicAdd(&g_cnt[recv[e]], 1);
}

__global__ void k_scan() {
    __shared__ int sp[1024];
    __shared__ int bins[ADIM];
    int t = threadIdx.x;
    if (t < ADIM) bins[t] = 0;
    __syncthreads();
    const int PER = 10;
    int base = t * PER;
    int loc[PER];
    int sum = 0;
    #pragma unroll
    for (int j = 0; j < PER; j++) {
        int idx = base + j;
        int v = 0;
        if (idx < N_NODES) {
            v = g_cnt[idx];
            atomicAdd(&bins[g_cls[idx]], 1);
        }
        loc[j] = sum; sum += v;
    }
    sp[t] = sum;
    __syncthreads();
    for (int d = 1; d < 1024; d <<= 1) {
        int v = (t >= d) ? sp[t - d] : 0;
        __syncthreads();
        sp[t] += v;
        __syncthreads();
    }
    int off = (t > 0) ? sp[t - 1] : 0;
    #pragma unroll
    for (int j = 0; j < PER; j++) {
        int idx = base + j;
        if (idx < N_NODES) { int o = off + loc[j]; g_off[idx] = o; g_cur[idx] = o; }
    }
    if (t == 0) {
        g_off[N_NODES] = sp[1023];
        int pc = 0;
        for (int a = 0; a < ADIM; a++) {
            g_pcoff[a] = pc; g_ccur[a] = pc;
            pc += ((bins[a] + 63) >> 6) << 6;     // pad each class to 64-row tiles
        }
        g_pcoff[ADIM] = pc;
    }
}

__global__ void k_fill(const int* __restrict__ recv) {
    int i = blockIdx.x * 256 + threadIdx.x;
    if (i < N_EDGES) {
        int r = recv[i];
        int p = atomicAdd(&g_cur[r], 1);
        g_csr[p] = i;
    }
    if (i < N_NODES) {
        int a = g_cls[i];
        int p = atomicAdd(&g_ccur[a], 1);
        g_clistp[p] = i;
    }
}

// ---------------- W4 transpose to fp16 (one-shot tiny kernel) ----------------
__global__ void k_w4t(const float* __restrict__ W4) {
    int gid = blockIdx.x * 256 + threadIdx.x;
    if (gid >= 64 * 512) return;
    int k = gid >> 9, n = gid & 511;
    g_W4T16[n * 64 + k] = __float2half_rn(W4[gid]);
}

// ---------------- edge MLP: 8 -> 64 -> 64 -> 64 (silu) -> fp16 ----------------
__global__ __launch_bounds__(128) void k_mlp(const float* __restrict__ ef,
                                             const float* __restrict__ W1,
                                             const float* __restrict__ W2,
                                             const float* __restrict__ W3) {
    __shared__ float sW1[RDIM * HDIM];
    __shared__ float sW2[HDIM * HDIM];
    __shared__ float sW3[HDIM * HDIM];
    int t = threadIdx.x;
    for (int i = t; i < RDIM * HDIM; i += 128) sW1[i] = W1[i];
    for (int i = t; i < HDIM * HDIM; i += 128) { sW2[i] = W2[i]; sW3[i] = W3[i]; }
    __syncthreads();

    int e = blockIdx.x * 128 + t;              // E % 128 == 0
    float x[RDIM];
    #pragma unroll
    for (int k = 0; k < RDIM; k++) x[k] = ef[e * RDIM + k];

    float h1[HDIM];
    #pragma unroll
    for (int j0 = 0; j0 < HDIM; j0 += 4) {
        float a0 = 0, a1 = 0, a2 = 0, a3 = 0;
        #pragma unroll
        for (int k = 0; k < RDIM; k++) {
            float xv = x[k];
            float4 w = *(const float4*)&sW1[k * HDIM + j0];
            a0 = fmaf(xv, w.x, a0); a1 = fmaf(xv, w.y, a1);
            a2 = fmaf(xv, w.z, a2); a3 = fmaf(xv, w.w, a3);
        }
        h1[j0 + 0] = silu(a0 * INV_SQRT_R);
        h1[j0 + 1] = silu(a1 * INV_SQRT_R);
        h1[j0 + 2] = silu(a2 * INV_SQRT_R);
        h1[j0 + 3] = silu(a3 * INV_SQRT_R);
    }

    float h2[HDIM];
    #pragma unroll
    for (int j0 = 0; j0 < HDIM; j0 += 4) {
        float a0 = 0, a1 = 0, a2 = 0, a3 = 0;
        #pragma unroll
        for (int k = 0; k < HDIM; k++) {
            float hv = h1[k];
            float4 w = *(const float4*)&sW2[k * HDIM + j0];
            a0 = fmaf(hv, w.x, a0); a1 = fmaf(hv, w.y, a1);
            a2 = fmaf(hv, w.z, a2); a3 = fmaf(hv, w.w, a3);
        }
        h2[j0 + 0] = silu(a0 * INV_SQRT_H);
        h2[j0 + 1] = silu(a1 * INV_SQRT_H);
        h2[j0 + 2] = silu(a2 * INV_SQRT_H);
        h2[j0 + 3] = silu(a3 * INV_SQRT_H);
    }

    #pragma unroll
    for (int j0 = 0; j0 < HDIM; j0 += 4) {
        float a0 = 0, a1 = 0, a2 = 0, a3 = 0;
        #pragma unroll
        for (int k = 0; k < HDIM; k++) {
            float hv = h2[k];
            float4 w = *(const float4*)&sW3[k * HDIM + j0];
            a0 = fmaf(hv, w.x, a0); a1 = fmaf(hv, w.y, a1);
            a2 = fmaf(hv, w.z, a2); a3 = fmaf(hv, w.w, a3);
        }
        __half2 p0 = __floats2half2_rn(silu(a0 * INV_SQRT_H), silu(a1 * INV_SQRT_H));
        __half2 p1 = __floats2half2_rn(silu(a2 * INV_SQRT_H), silu(a3 * INV_SQRT_H));
        *(__half2*)&g_h16[e * HDIM + j0]     = p0;
        *(__half2*)&g_h16[e * HDIM + j0 + 2] = p1;
    }
}

// ---------------- tp_w = h @ W4 / sqrt(H) via single-pass fp16 mma.sync ----------------
// CTA: 64 edges x 512 outputs (4 chunks of 128). 4 warps: warp tile 32 edges x 64 out.
// fp16 in, fp32 accum, fp16 out. Smem rows 36 words: ldmatrix conflict-free (verified R11/12).
// Epilogue staged through smem (68-word rows) -> fully coalesced STG.128.
__global__ __launch_bounds__(128) void k_tpw() {
    __shared__ __align__(16) unsigned sA[64 * 36];    // 9216 B
    __shared__ __align__(16) unsigned sB[128 * 36];   // 18432 B (reused as 64x68 stage)
    unsigned sbA = smem_u32(sA), sbB = smem_u32(sB);

    int t = threadIdx.x, lane = t & 31, wid = t >> 5;
    int e0 = blockIdx.x * 64;                 // E = 2500 * 64

    // A fill: 64 rows x 8 uint4 (vectorized)
    for (int i = t; i < 64 * 8; i += 128) {
        int row = i >> 3, u = i & 7;
        uint4 v = ((const uint4*)g_h16)[(size_t)(e0 + row) * 8 + u];
        *(uint4*)&sA[row * 36 + u * 4] = v;
    }

    int g = lane >> 2, q = lane & 3;
    int m0 = (wid >> 1) * 32;
    int n0 = (wid & 1) * 64;

    unsigned aoff = (unsigned)((lane & 15) * 144 + ((lane >> 4) << 4)) + m0 * 144;
    unsigned boff = (unsigned)((((lane >> 4) << 3) + (lane & 7)) * 144 + (((lane >> 3) & 1) << 4)) + n0 * 144;
    unsigned Ab = sbA + aoff;
    unsigned Bb = sbB + boff;

    for (int nh = 0; nh < 4; nh++) {
        __syncthreads();                      // stage readers done / A fill (iter 0)
        for (int i = t; i < 128 * 8; i += 128) {
            int n = i >> 3, u = i & 7;
            uint4 v = ((const uint4*)g_W4T16)[(nh * 128 + n) * 8 + u];
            *(uint4*)&sB[n * 36 + u * 4] = v;
        }
        __syncthreads();

        float acc[2][8][4];
        #pragma unroll
        for (int mt = 0; mt < 2; mt++)
            #pragma unroll
            for (int nt = 0; nt < 8; nt++)
                #pragma unroll
                for (int j = 0; j < 4; j++) acc[mt][nt][j] = 0.f;

        #pragma unroll
        for (int kt = 0; kt < 4; kt++) {
            unsigned a[2][4];
            #pragma unroll
            for (int mt = 0; mt < 2; mt++) {
                asm volatile("ldmatrix.sync.aligned.m8n8.x4.shared.b16 {%0,%1,%2,%3}, [%4];"
                    : "=r"(a[mt][0]), "=r"(a[mt][1]), "=r"(a[mt][2]), "=r"(a[mt][3])
                    : "r"(Ab + mt * 2304 + kt * 32));
            }
            #pragma unroll
            for (int j = 0; j < 4; j++) {
                unsigned b[4];
                asm volatile("ldmatrix.sync.aligned.m8n8.x4.shared.b16 {%0,%1,%2,%3}, [%4];"
                    : "=r"(b[0]), "=r"(b[1]), "=r"(b[2]), "=r"(b[3])
                    : "r"(Bb + j * 2304 + kt * 32));
                #pragma unroll
                for (int h = 0; h < 2; h++) {
                    int nt = j * 2 + h;
                    #pragma unroll
                    for (int mt = 0; mt < 2; mt++) {
                        asm volatile(
                            "mma.sync.aligned.m16n8k16.row.col.f32.f16.f16.f32 "
                            "{%0,%1,%2,%3}, {%4,%5,%6,%7}, {%8,%9}, {%0,%1,%2,%3};"
                            : "+f"(acc[mt][nt][0]), "+f"(acc[mt][nt][1]),
                              "+f"(acc[mt][nt][2]), "+f"(acc[mt][nt][3])
                            : "r"(a[mt][0]), "r"(a[mt][1]), "r"(a[mt][2]), "r"(a[mt][3]),
                              "r"(b[h * 2]), "r"(b[h * 2 + 1]));
                    }
                }
            }
        }

        // staged epilogue: sB reused as 64 rows x 68 words (stride ≡4 mod 32 -> conflict-free)
        __syncthreads();                      // all fragment reads of sB done
        #pragma unroll
        for (int mt = 0; mt < 2; mt++) {
            int r = m0 + mt * 16 + g;
            #pragma unroll
            for (int nt = 0; nt < 8; nt++) {
                int colw = (n0 + nt * 8 + q * 2) >> 1;
                __half2 d0 = __floats2half2_rn(acc[mt][nt][0] * INV_SQRT_H,
                                               acc[mt][nt][1] * INV_SQRT_H);
                __half2 d1 = __floats2half2_rn(acc[mt][nt][2] * INV_SQRT_H,
                                               acc[mt][nt][3] * INV_SQRT_H);
                sB[r * 68 + colw]       = *(unsigned*)&d0;
                sB[(r + 8) * 68 + colw] = *(unsigned*)&d1;
            }
        }
        __syncthreads();
        // coalesced store: per warp-instr 2 rows x 256B contiguous
        #pragma unroll
        for (int it = 0; it < 8; it++) {
            int r = wid * 16 + it * 2 + (lane >> 4);
            int cw = lane & 15;
            uint4 v = *(uint4*)&sB[r * 68 + cw * 4];
            *(uint4*)&g_tpw16[(size_t)(e0 + r) * 512 + nh * 128 + cw * 8] = v;
        }
    }
}

// ---------------- node up-projections s, v ----------------
__global__ __launch_bounds__(256) void k_sv(const float* __restrict__ nf,
                                            const float* __restrict__ Wu0,
                                            const float* __restrict__ Wu1) {
    __shared__ float sW[64 * 128];   // 32 KB
    __shared__ float sX[32 * 64];    // 8 KB
    int t = threadIdx.x;
    int comp = blockIdx.y;
    int n0 = blockIdx.x * 32;
    const float* W = (comp == 0) ? Wu0 : Wu1;
    int nb = (t >> 5) << 2, ob = (t & 31) << 2;
    float acc[4][4] = {};
    for (int k0 = 0; k0 < CDIM; k0 += 64) {
        __syncthreads();
        for (int i = t; i < 64 * 128; i += 256) {
            int kk = i >> 7, d = i & 127;
            sW[i] = W[(k0 + kk) * 128 + d];
        }
        for (int i = t; i < 32 * 64; i += 256) {
            int r = i >> 6, kk = i & 63;
            int n = n0 + r;
            float v = 0.f;
            if (n < N_NODES) {
                if (comp == 0) v = nf[n * 512 + k0 + kk];
                else           v = nf[n * 512 + 128 + (k0 + kk) * 3 + (comp - 1)];
            }
            sX[i] = v;
        }
        __syncthreads();
        #pragma unroll
        for (int kk = 0; kk < 64; kk++) {
            float a0 = sX[(nb + 0) * 64 + kk];
            float a1 = sX[(nb + 1) * 64 + kk];
            float a2 = sX[(nb + 2) * 64 + kk];
            float a3 = sX[(nb + 3) * 64 + kk];
            float4 w = *(const float4*)&sW[kk * 128 + ob];
            acc[0][0] += a0 * w.x; acc[0][1] += a0 * w.y; acc[0][2] += a0 * w.z; acc[0][3] += a0 * w.w;
            acc[1][0] += a1 * w.x; acc[1][1] += a1 * w.y; acc[1][2] += a1 * w.z; acc[1][3] += a1 * w.w;
            acc[2][0] += a2 * w.x; acc[2][1] += a2 * w.y; acc[2][2] += a2 * w.z; acc[2][3] += a2 * w.w;
            acc[3][0] += a3 * w.x; acc[3][1] += a3 * w.y; acc[3][2] += a3 * w.z; acc[3][3] += a3 * w.w;
        }
    }
    #pragma unroll
    for (int r = 0; r < 4; r++) {
        int n = n0 + nb + r;
        if (n >= N_NODES) continue;
        if (comp == 0) {
            float4 o = make_float4(acc[r][0] * INV_SQRT_C, acc[r][1] * INV_SQRT_C,
                                   acc[r][2] * INV_SQRT_C, acc[r][3] * INV_SQRT_C);
            *(float4*)&g_s[n * 128 + ob] = o;
        } else {
            #pragma unroll
            for (int c = 0; c < 4; c++)
                g_v[n * 384 + (ob + c) * 3 + (comp - 1)] = acc[r][c] * INV_SQRT_C;
        }
    }
}

// ---------------- fused weights: WcT[a][col][k] = (W_lin @ W_skip[:,a,:])^T, fp16 ----------------
__global__ __launch_bounds__(256) void k_wc(const float* __restrict__ Wl0,
                                            const float* __restrict__ Wl1,
                                            const float* __restrict__ Wsk0,
                                            const float* __restrict__ Wsk1) {
    __shared__ float sSk[64 * 128];  // 32 KB
    __shared__ float sWl[16 * 64];   // 4 KB
    int t = threadIdx.x;
    int c0 = blockIdx.x * 16;
    int a = blockIdx.y;
    int pair = blockIdx.z;
    const float* Wl  = pair ? Wl1  : Wl0;
    const float* Wsk = pair ? Wsk1 : Wsk0;
    __half* WcT = pair ? g_WcT1 : g_WcT0;
    int d = t & 127, half = t >> 7;
    float acc[8] = {};
    for (int m0 = 0; m0 < 128; m0 += 64) {
        __syncthreads();
        for (int i = t; i < 64 * 128; i += 256) {
            int mm = i >> 7, dd = i & 127;
            sSk[i] = Wsk[((m0 + mm) * ADIM + a) * 128 + dd];
        }
        for (int i = t; i < 16 * 64; i += 256) {
            int cc = i >> 6, mm = i & 63;
            sWl[i] = Wl[(c0 + cc) * 128 + m0 + mm];
        }
        __syncthreads();
        #pragma unroll 8
        for (int m = 0; m < 64; m++) {
            float sk = sSk[m * 128 + d];
            #pragma unroll
            for (int j = 0; j < 8; j++) {
                int cc = half + 2 * j;
                acc[j] = fmaf(sWl[cc * 64 + m], sk, acc[j]);
            }
        }
    }
    #pragma unroll
    for (int j = 0; j < 8; j++) {
        int c = c0 + half + 2 * j;   // k index 0..255
        WcT[(a * 128 + d) * 256 + c] = __float2half_rn(acc[j]);
    }
}

// ---------------- edge aggregation: CSR gather into fp16 M planes ----------------
__global__ __launch_bounds__(128) void k_agg(const int* __restrict__ sender,
                                             const float* __restrict__ ea) {
    int n = blockIdx.x;
    int c = threadIdx.x;
    int beg = g_off[n], end = g_off[n + 1];
    float ms1 = 0, ms2 = 0;
    float mv10 = 0, mv11 = 0, mv12 = 0;
    float mv20 = 0, mv21 = 0, mv22 = 0;
    for (int p = beg; p < end; p++) {
        int e = g_csr[p];
        int sj = sender[e];
        float4 y = *(const float4*)&ea[e * 4];
        const __half* tw = g_tpw16 + (size_t)e * 512;
        float ws1 = __half2float(tw[c]);
        float ws2 = __half2float(tw[128 + c]);
        float wv1 = __half2float(tw[256 + c]);
        float wv2 = __half2float(tw[384 + c]);
        float sv = g_s[sj * 128 + c];
        const float* vp = &g_v[sj * 384 + c * 3];
        float v0 = vp[0], v1 = vp[1], v2 = vp[2];
        ms1 = fmaf(ws1 * sv, y.x, ms1);
        float dot = v0 * y.y + v1 * y.z + v2 * y.w;
        ms2 = fmaf(ws2, dot, ms2);
        float a1 = wv1 * sv;
        mv10 = fmaf(a1, y.y, mv10); mv11 = fmaf(a1, y.z, mv11); mv12 = fmaf(a1, y.w, mv12);
        float a2 = wv2 * y.x;
        mv20 = fmaf(a2, v0, mv20); mv21 = fmaf(a2, v1, mv21); mv22 = fmaf(a2, v2, mv22);
    }
    const int PL = N_NODES * 256;
    g_M16[n * 256 + c]          = __float2half_rn(ms1);
    g_M16[n * 256 + 128 + c]    = __float2half_rn(ms2 * INV_SQRT3);
    g_M16[PL + n * 256 + c]         = __float2half_rn(mv10);
    g_M16[PL + n * 256 + 128 + c]   = __float2half_rn(mv20);
    g_M16[2*PL + n * 256 + c]       = __float2half_rn(mv11);
    g_M16[2*PL + n * 256 + 128 + c] = __float2half_rn(mv21);
    g_M16[3*PL + n * 256 + c]       = __float2half_rn(mv12);
    g_M16[3*PL + n * 256 + 128 + c] = __float2half_rn(mv22);
}

// ---------------- class-batched output GEMM via fp16 mma: out = M @ Wc[a] * OUT_SCALE ----
// Per CTA: 64 class-sorted nodes x 128 cols, K=256 in 4 chunks. Same fragment layout as k_tpw.
__global__ __launch_bounds__(128) void k_final(float* __restrict__ out) {
    __shared__ __align__(16) unsigned sA[64 * 36];
    __shared__ __align__(16) unsigned sB[128 * 36];
    __shared__ int sN[64];
    unsigned sbA = smem_u32(sA), sbB = smem_u32(sB);

    int t = threadIdx.x, lane = t & 31, wid = t >> 5;
    int comp = blockIdx.y;
    int row0 = blockIdx.x * 64;
    if (row0 >= g_pcoff[ADIM]) return;
    int a = 0;
    while (row0 >= g_pcoff[a + 1]) a++;

    if (t < 64) sN[t] = g_clistp[row0 + t];
    __syncthreads();

    const uint4* M = (const uint4*)g_M16 + (size_t)comp * (N_NODES * 32);
    const uint4* B = (const uint4*)(comp == 0 ? g_WcT0 : g_WcT1) + a * 128 * 32;

    int g = lane >> 2, q = lane & 3;
    int m0 = (wid >> 1) * 32;
    int n0 = (wid & 1) * 64;
    unsigned aoff = (unsigned)((lane & 15) * 144 + ((lane >> 4) << 4)) + m0 * 144;
    unsigned boff = (unsigned)((((lane >> 4) << 3) + (lane & 7)) * 144 + (((lane >> 3) & 1) << 4)) + n0 * 144;
    unsigned Ab = sbA + aoff;
    unsigned Bb = sbB + boff;

    float acc[2][8][4];
    #pragma unroll
    for (int mt = 0; mt < 2; mt++)
        #pragma unroll
        for (int nt = 0; nt < 8; nt++)
            #pragma unroll
            for (int j = 0; j < 4; j++) acc[mt][nt][j] = 0.f;

    for (int kc = 0; kc < 4; kc++) {
        __syncthreads();
        for (int i = t; i < 64 * 8; i += 128) {
            int row = i >> 3, u = i & 7;
            int node = sN[row];
            uint4 v = make_uint4(0, 0, 0, 0);
            if (node >= 0) v = M[node * 32 + kc * 8 + u];
            *(uint4*)&sA[row * 36 + u * 4] = v;
        }
        for (int i = t; i < 128 * 8; i += 128) {
            int col = i >> 3, u = i & 7;
            uint4 v = B[col * 32 + kc * 8 + u];
            *(uint4*)&sB[col * 36 + u * 4] = v;
        }
        __syncthreads();

        #pragma unroll
        for (int kt = 0; kt < 4; kt++) {
            unsigned af[2][4];
            #pragma unroll
            for (int mt = 0; mt < 2; mt++) {
                asm volatile("ldmatrix.sync.aligned.m8n8.x4.shared.b16 {%0,%1,%2,%3}, [%4];"
                    : "=r"(af[mt][0]), "=r"(af[mt][1]), "=r"(af[mt][2]), "=r"(af[mt][3])
                    : "r"(Ab + mt * 2304 + kt * 32));
            }
            #pragma unroll
            for (int j = 0; j < 4; j++) {
                unsigned bf[4];
                asm volatile("ldmatrix.sync.aligned.m8n8.x4.shared.b16 {%0,%1,%2,%3}, [%4];"
                    : "=r"(bf[0]), "=r"(bf[1]), "=r"(bf[2]), "=r"(bf[3])
                    : "r"(Bb + j * 2304 + kt * 32));
                #pragma unroll
                for (int h = 0; h < 2; h++) {
                    int nt = j * 2 + h;
                    #pragma unroll
                    for (int mt = 0; mt < 2; mt++) {
                        asm volatile(
                            "mma.sync.aligned.m16n8k16.row.col.f32.f16.f16.f32 "
                            "{%0,%1,%2,%3}, {%4,%5,%6,%7}, {%8,%9}, {%0,%1,%2,%3};"
                            : "+f"(acc[mt][nt][0]), "+f"(acc[mt][nt][1]),
                              "+f"(acc[mt][nt][2]), "+f"(acc[mt][nt][3])
                            : "r"(af[mt][0]), "r"(af[mt][1]), "r"(af[mt][2]), "r"(af[mt][3]),
                              "r"(bf[h * 2]), "r"(bf[h * 2 + 1]));
                    }
                }
            }
        }
    }

    // epilogue
    #pragma unroll
    for (int mt = 0; mt < 2; mt++) {
        int r = m0 + mt * 16 + g;
        int nodeA = sN[r], nodeB = sN[r + 8];
        #pragma unroll
        for (int nt = 0; nt < 8; nt++) {
            int col = n0 + nt * 8 + q * 2;
            if (comp == 0) {
                if (nodeA >= 0)
                    *(float2*)&out[nodeA * 512 + col] =
                        make_float2(acc[mt][nt][0] * OUT_SCALE, acc[mt][nt][1] * OUT_SCALE);
                if (nodeB >= 0)
                    *(float2*)&out[nodeB * 512 + col] =
                        make_float2(acc[mt][nt][2] * OUT_SCALE, acc[mt][nt][3] * OUT_SCALE);
            } else {
                int cb = 128 + (comp - 1);
                if (nodeA >= 0) {
                    out[nodeA * 512 + cb + col * 3]       = acc[mt][nt][0] * OUT_SCALE;
                    out[nodeA * 512 + cb + (col + 1) * 3] = acc[mt][nt][1] * OUT_SCALE;
                }
                if (nodeB >= 0) {
                    out[nodeB * 512 + cb + col * 3]       = acc[mt][nt][2] * OUT_SCALE;
                    out[nodeB * 512 + cb + (col + 1) * 3] = acc[mt][nt][3] * OUT_SCALE;
                }
            }
        }
    }
}

// ---------------- launch ----------------
extern "C" void kernel_launch(void* const* d_in, const int* in_sizes, int n_in,
                              void* d_out, int out_size) {
    const float* node_attrs = (const float*)d_in[0];
    const float* node_feats = (const float*)d_in[1];
    const float* edge_attrs = (const float*)d_in[2];
    const float* edge_feats = (const float*)d_in[3];
    const int*   edge_index = (const int*)d_in[4];
    const float* W_up0  = (const float*)d_in[5];
    const float* W_up1  = (const float*)d_in[6];
    const float* W_mlp1 = (const float*)d_in[7];
    const float* W_mlp2 = (const float*)d_in[8];
    const float* W_mlp3 = (const float*)d_in[9];
    const float* W_mlp4 = (const float*)d_in[10];
    const float* W_lin0 = (const float*)d_in[11];
    const float* W_lin1 = (const float*)d_in[12];
    const float* W_skip0 = (const float*)d_in[13];
    const float* W_skip1 = (const float*)d_in[14];
    float* out = (float*)d_out;

    const int* sender = edge_index;            // row 0
    const int* recv   = edge_index + N_EDGES;  // row 1

    // Launch order: k_tpw kept at slot 4 (ncu capture slot).
    k_w4t<<<128, 256>>>(W_mlp4);                                     // 1
    k_cls<<<(NPAD + 255) / 256, 256>>>(node_attrs);                  // 2
    k_mlp<<<N_EDGES / 128, 128>>>(edge_feats, W_mlp1, W_mlp2, W_mlp3); // 3
    k_tpw<<<N_EDGES / 64, 128>>>();                                  // 4  (tensor core)
    k_count<<<N_EDGES / 256, 256>>>(recv);                           // 5
    k_sv<<<dim3((N_NODES + 31) / 32, 4), 256>>>(node_feats, W_up0, W_up1); // 6
    k_scan<<<1, 1024>>>();                                           // 7
    k_fill<<<N_EDGES / 256, 256>>>(recv);                            // 8
    k_wc<<<dim3(16, ADIM, 2), 256>>>(W_lin0, W_lin1, W_skip0, W_skip1); // 9
    k_agg<<<N_NODES, 128>>>(sender, edge_attrs);                     // 10
    k_final<<<dim3((NPAD + 63) / 64, 4), 128>>>(out);                // 11 (tensor core)
}

// round 15
// speedup vs baseline: 2.8002x; 1.6525x over previous
#include <cuda_runtime.h>
#include <cuda_fp16.h>
#include <math.h>

#define N_NODES 10000
#define N_EDGES 160000
#define CDIM 128
#define ADIM 10
#define RDIM 8
#define HDIM 64
#define NPAD 10688

#define INV_SQRT_R 0.35355339059327373f
#define INV_SQRT_H 0.125f
#define INV_SQRT_C 0.08838834764831845f
#define INV_SQRT3  0.5773502691896258f
// 1 / (sqrt(2C)*AVG_NEI * sqrt(C*A)) = 1/(256 * sqrt(1280))
#define OUT_SCALE  (1.0f / (256.0f * 35.77708763999664f))

// ---------------- scratch (device globals; no allocations) ----------------
__device__ __half g_h16[N_EDGES * HDIM];              // 20 MB (fp16 edge MLP out)
__device__ __half g_W4T16[512 * 64];                  // 64 KB (W4 transposed, fp16)
__device__ __half g_W2T16[64 * 64];
__device__ __half g_W3T16[64 * 64];
__device__ __half g_tpw16[(size_t)N_EDGES * 512];     // 163 MB (fp16 tp_w)
__device__ float g_s[N_NODES * CDIM];                 // 5 MB
__device__ float g_v[N_NODES * CDIM * 3];             // 15 MB, planar [n][comp][128]
__device__ __half g_M16[4 * N_NODES * 256];           // 20 MB (fp16 M planes)
__device__ __half g_WcT0[ADIM * 128 * 256];           // 640 KB (fused W, transposed fp16)
__device__ __half g_WcT1[ADIM * 128 * 256];           // 640 KB
__device__ int   g_cnt[N_NODES];
__device__ int   g_off[N_NODES + 1];
__device__ int   g_cur[N_NODES];
__device__ int   g_csr[N_EDGES];
__device__ int   g_cls[N_NODES];
__device__ int   g_pcoff[ADIM + 1];
__device__ int   g_ccur[ADIM];
__device__ int   g_clistp[NPAD];

// fast silu: MUFU-based exp + approx divide (rel err ~1e-6, fine vs 1e-3 gate)
__device__ __forceinline__ float silu(float x) {
    float e = __expf(-x);
    return __fdividef(x, 1.0f + e);
}

__device__ __forceinline__ unsigned smem_u32(const void* p) {
    unsigned a;
    asm("{ .reg .u64 t; cvta.to.shared.u64 t, %1; cvt.u32.u64 %0, t; }" : "=r"(a) : "l"(p));
    return a;
}

#define LDSM4(r0, r1, r2, r3, addr) \
    asm volatile("ldmatrix.sync.aligned.m8n8.x4.shared.b16 {%0,%1,%2,%3}, [%4];" \
        : "=r"(r0), "=r"(r1), "=r"(r2), "=r"(r3) : "r"(addr))

#define MMA16816(acc, a0, a1, a2, a3, b0, b1) \
    asm volatile("mma.sync.aligned.m16n8k16.row.col.f32.f16.f16.f32 " \
        "{%0,%1,%2,%3}, {%4,%5,%6,%7}, {%8,%9}, {%0,%1,%2,%3};" \
        : "+f"((acc)[0]), "+f"((acc)[1]), "+f"((acc)[2]), "+f"((acc)[3]) \
        : "r"(a0), "r"(a1), "r"(a2), "r"(a3), "r"(b0), "r"(b1))

// ---------------- plumbing ----------------
__global__ void k_cls(const float* __restrict__ na) {
    int n = blockIdx.x * 256 + threadIdx.x;
    if (n < NPAD) g_clistp[n] = -1;
    if (n >= N_NODES) return;
    g_cnt[n] = 0;
    int a = 0;
    #pragma unroll
    for (int j = 0; j < ADIM; j++)
        if (na[n * ADIM + j] > 0.5f) a = j;
    g_cls[n] = a;
}

__global__ void k_count(const int* __restrict__ recv) {
    int e = blockIdx.x * 256 + threadIdx.x;   // E % 256 == 0
    atomicAdd(&g_cnt[recv[e]], 1);
}

__global__ void k_scan() {
    __shared__ int sp[1024];
    __shared__ int bins[ADIM];
    int t = threadIdx.x;
    if (t < ADIM) bins[t] = 0;
    __syncthreads();
    const int PER = 10;
    int base = t * PER;
    int loc[PER];
    int sum = 0;
    #pragma unroll
    for (int j = 0; j < PER; j++) {
        int idx = base + j;
        int v = 0;
        if (idx < N_NODES) {
            v = g_cnt[idx];
            atomicAdd(&bins[g_cls[idx]], 1);
        }
        loc[j] = sum; sum += v;
    }
    sp[t] = sum;
    __syncthreads();
    for (int d = 1; d < 1024; d <<= 1) {
        int v = (t >= d) ? sp[t - d] : 0;
        __syncthreads();
        sp[t] += v;
        __syncthreads();
    }
    int off = (t > 0) ? sp[t - 1] : 0;
    #pragma unroll
    for (int j = 0; j < PER; j++) {
        int idx = base + j;
        if (idx < N_NODES) { int o = off + loc[j]; g_off[idx] = o; g_cur[idx] = o; }
    }
    if (t == 0) {
        g_off[N_NODES] = sp[1023];
        int pc = 0;
        for (int a = 0; a < ADIM; a++) {
            g_pcoff[a] = pc; g_ccur[a] = pc;
            pc += ((bins[a] + 63) >> 6) << 6;     // pad each class to 64-row tiles
        }
        g_pcoff[ADIM] = pc;
    }
}

__global__ void k_fill(const int* __restrict__ recv) {
    int i = blockIdx.x * 256 + threadIdx.x;
    if (i < N_EDGES) {
        int r = recv[i];
        int p = atomicAdd(&g_cur[r], 1);
        g_csr[p] = i;
    }
    if (i < N_NODES) {
        int a = g_cls[i];
        int p = atomicAdd(&g_ccur[a], 1);
        g_clistp[p] = i;
    }
}

// ---------------- weight transposes to fp16 (one-shot tiny kernel) ----------------
__global__ void k_w4t(const float* __restrict__ W4, const float* __restrict__ W2,
                      const float* __restrict__ W3) {
    int gid = blockIdx.x * 256 + threadIdx.x;
    if (gid < 64 * 512) {
        int k = gid >> 9, n = gid & 511;
        g_W4T16[n * 64 + k] = __float2half_rn(W4[gid]);
    }
    int r = gid - 64 * 512;
    if (r >= 0 && r < 64 * 64) {
        int k = r >> 6, n = r & 63;
        g_W2T16[n * 64 + k] = __float2half_rn(W2[r]);
        g_W3T16[n * 64 + k] = __float2half_rn(W3[r]);
    }
}

// ---------------- edge MLP: 8 -> 64 (scalar) -> 64 -> 64 (fp16 mma) ----------------
// CTA: 64 edges, 128 threads / 4 warps. Warp tile 32 edges x 32 out per mma layer.
// Fragment/ldmatrix layout identical to verified k_tpw (36-word rows).
__global__ __launch_bounds__(128) void k_mlp(const float* __restrict__ ef,
                                             const float* __restrict__ W1) {
    __shared__ float sW1[RDIM * HDIM];
    __shared__ __align__(16) unsigned sA[64 * 36];
    __shared__ __align__(16) unsigned sC[64 * 36];
    __shared__ __align__(16) unsigned sB[64 * 36];
    unsigned sbA = smem_u32(sA), sbC = smem_u32(sC), sbB = smem_u32(sB);

    int t = threadIdx.x, lane = t & 31, wid = t >> 5;
    int e0 = blockIdx.x * 64;                 // E = 2500 * 64

    for (int i = t; i < RDIM * HDIM; i += 128) sW1[i] = W1[i];
    // W2T -> sB (64 rows x 32 words, 36-word stride)
    for (int i = t; i < 64 * 8; i += 128) {
        int n = i >> 3, u = i & 7;
        uint4 v = ((const uint4*)g_W2T16)[n * 8 + u];
        *(uint4*)&sB[n * 36 + u * 4] = v;
    }
    __syncthreads();

    // ---- layer 1 (scalar): 2 threads per edge, 32 outs each ----
    {
        int e1 = t >> 1, oh = t & 1;
        const float4* xf = (const float4*)&ef[(size_t)(e0 + e1) * 8];
        float4 xa = xf[0], xb = xf[1];
        float x[8] = {xa.x, xa.y, xa.z, xa.w, xb.x, xb.y, xb.z, xb.w};
        #pragma unroll
        for (int j = 0; j < 16; j++) {
            float a0 = 0.f, a1 = 0.f;
            #pragma unroll
            for (int k = 0; k < 8; k++) {
                float xv = x[k];
                a0 = fmaf(xv, sW1[k * 64 + oh * 32 + 2 * j], a0);
                a1 = fmaf(xv, sW1[k * 64 + oh * 32 + 2 * j + 1], a1);
            }
            __half2 p = __floats2half2_rn(silu(a0 * INV_SQRT_R), silu(a1 * INV_SQRT_R));
            sA[e1 * 36 + oh * 16 + j] = *(unsigned*)&p;
        }
    }
    __syncthreads();

    int g = lane >> 2, q = lane & 3;
    int m0 = (wid >> 1) * 32;
    int n0 = (wid & 1) * 32;
    unsigned aoff = (unsigned)((lane & 15) * 144 + ((lane >> 4) << 4)) + m0 * 144;
    unsigned boff = (unsigned)((((lane >> 4) << 3) + (lane & 7)) * 144 + (((lane >> 3) & 1) << 4)) + n0 * 144;

    // ---- layer 2 mma ----
    {
        float acc[2][4][4];
        #pragma unroll
        for (int mt = 0; mt < 2; mt++)
            #pragma unroll
            for (int nt = 0; nt < 4; nt++)
                #pragma unroll
                for (int j = 0; j < 4; j++) acc[mt][nt][j] = 0.f;
        #pragma unroll
        for (int kt = 0; kt < 4; kt++) {
            unsigned a[2][4];
            #pragma unroll
            for (int mt = 0; mt < 2; mt++)
                LDSM4(a[mt][0], a[mt][1], a[mt][2], a[mt][3], sbA + aoff + mt * 2304 + kt * 32);
            #pragma unroll
            for (int j = 0; j < 2; j++) {
                unsigned b[4];
                LDSM4(b[0], b[1], b[2], b[3], sbB + boff + j * 2304 + kt * 32);
                #pragma unroll
                for (int h = 0; h < 2; h++) {
                    int nt = j * 2 + h;
                    #pragma unroll
                    for (int mt = 0; mt < 2; mt++)
                        MMA16816(acc[mt][nt], a[mt][0], a[mt][1], a[mt][2], a[mt][3],
                                 b[h * 2], b[h * 2 + 1]);
                }
            }
        }
        // epilogue: silu -> fp16 -> sC (bank map 4g+q: conflict-free)
        #pragma unroll
        for (int mt = 0; mt < 2; mt++) {
            int r = m0 + mt * 16 + g;
            #pragma unroll
            for (int nt = 0; nt < 4; nt++) {
                int colw = (n0 + nt * 8 + q * 2) >> 1;
                __half2 d0 = __floats2half2_rn(silu(acc[mt][nt][0] * INV_SQRT_H),
                                               silu(acc[mt][nt][1] * INV_SQRT_H));
                __half2 d1 = __floats2half2_rn(silu(acc[mt][nt][2] * INV_SQRT_H),
                                               silu(acc[mt][nt][3] * INV_SQRT_H));
                sC[r * 36 + colw]       = *(unsigned*)&d0;
                sC[(r + 8) * 36 + colw] = *(unsigned*)&d1;
            }
        }
    }
    __syncthreads();
    // W3T -> sB
    for (int i = t; i < 64 * 8; i += 128) {
        int n = i >> 3, u = i & 7;
        uint4 v = ((const uint4*)g_W3T16)[n * 8 + u];
        *(uint4*)&sB[n * 36 + u * 4] = v;
    }
    __syncthreads();

    // ---- layer 3 mma ----
    {
        float acc[2][4][4];
        #pragma unroll
        for (int mt = 0; mt < 2; mt++)
            #pragma unroll
            for (int nt = 0; nt < 4; nt++)
                #pragma unroll
                for (int j = 0; j < 4; j++) acc[mt][nt][j] = 0.f;
        #pragma unroll
        for (int kt = 0; kt < 4; kt++) {
            unsigned a[2][4];
            #pragma unroll
            for (int mt = 0; mt < 2; mt++)
                LDSM4(a[mt][0], a[mt][1], a[mt][2], a[mt][3], sbC + aoff + mt * 2304 + kt * 32);
            #pragma unroll
            for (int j = 0; j < 2; j++) {
                unsigned b[4];
                LDSM4(b[0], b[1], b[2], b[3], sbB + boff + j * 2304 + kt * 32);
                #pragma unroll
                for (int h = 0; h < 2; h++) {
                    int nt = j * 2 + h;
                    #pragma unroll
                    for (int mt = 0; mt < 2; mt++)
                        MMA16816(acc[mt][nt], a[mt][0], a[mt][1], a[mt][2], a[mt][3],
                                 b[h * 2], b[h * 2 + 1]);
                }
            }
        }
        // epilogue: silu -> fp16 -> g_h16 (scattered half2; 20 MB total, minor)
        #pragma unroll
        for (int mt = 0; mt < 2; mt++) {
            int er = e0 + m0 + mt * 16 + g;
            #pragma unroll
            for (int nt = 0; nt < 4; nt++) {
                int col = n0 + nt * 8 + q * 2;
                __half2 d0 = __floats2half2_rn(silu(acc[mt][nt][0] * INV_SQRT_H),
                                               silu(acc[mt][nt][1] * INV_SQRT_H));
                __half2 d1 = __floats2half2_rn(silu(acc[mt][nt][2] * INV_SQRT_H),
                                               silu(acc[mt][nt][3] * INV_SQRT_H));
                *(__half2*)&g_h16[(size_t)er * 64 + col]       = d0;
                *(__half2*)&g_h16[(size_t)(er + 8) * 64 + col] = d1;
            }
        }
    }
}

// ---------------- tp_w = h @ W4 / sqrt(H) via single-pass fp16 mma.sync ----------------
// (verified R14 version, unchanged)
__global__ __launch_bounds__(128) void k_tpw() {
    __shared__ __align__(16) unsigned sA[64 * 36];    // 9216 B
    __shared__ __align__(16) unsigned sB[128 * 36];   // 18432 B (reused as 64x68 stage)
    unsigned sbA = smem_u32(sA), sbB = smem_u32(sB);

    int t = threadIdx.x, lane = t & 31, wid = t >> 5;
    int e0 = blockIdx.x * 64;                 // E = 2500 * 64

    for (int i = t; i < 64 * 8; i += 128) {
        int row = i >> 3, u = i & 7;
        uint4 v = ((const uint4*)g_h16)[(size_t)(e0 + row) * 8 + u];
        *(uint4*)&sA[row * 36 + u * 4] = v;
    }

    int g = lane >> 2, q = lane & 3;
    int m0 = (wid >> 1) * 32;
    int n0 = (wid & 1) * 64;

    unsigned aoff = (unsigned)((lane & 15) * 144 + ((lane >> 4) << 4)) + m0 * 144;
    unsigned boff = (unsigned)((((lane >> 4) << 3) + (lane & 7)) * 144 + (((lane >> 3) & 1) << 4)) + n0 * 144;
    unsigned Ab = sbA + aoff;
    unsigned Bb = sbB + boff;

    for (int nh = 0; nh < 4; nh++) {
        __syncthreads();
        for (int i = t; i < 128 * 8; i += 128) {
            int n = i >> 3, u = i & 7;
            uint4 v = ((const uint4*)g_W4T16)[(nh * 128 + n) * 8 + u];
            *(uint4*)&sB[n * 36 + u * 4] = v;
        }
        __syncthreads();

        float acc[2][8][4];
        #pragma unroll
        for (int mt = 0; mt < 2; mt++)
            #pragma unroll
            for (int nt = 0; nt < 8; nt++)
                #pragma unroll
                for (int j = 0; j < 4; j++) acc[mt][nt][j] = 0.f;

        #pragma unroll
        for (int kt = 0; kt < 4; kt++) {
            unsigned a[2][4];
            #pragma unroll
            for (int mt = 0; mt < 2; mt++)
                LDSM4(a[mt][0], a[mt][1], a[mt][2], a[mt][3], Ab + mt * 2304 + kt * 32);
            #pragma unroll
            for (int j = 0; j < 4; j++) {
                unsigned b[4];
                LDSM4(b[0], b[1], b[2], b[3], Bb + j * 2304 + kt * 32);
                #pragma unroll
                for (int h = 0; h < 2; h++) {
                    int nt = j * 2 + h;
                    #pragma unroll
                    for (int mt = 0; mt < 2; mt++)
                        MMA16816(acc[mt][nt], a[mt][0], a[mt][1], a[mt][2], a[mt][3],
                                 b[h * 2], b[h * 2 + 1]);
                }
            }
        }

        __syncthreads();
        #pragma unroll
        for (int mt = 0; mt < 2; mt++) {
            int r = m0 + mt * 16 + g;
            #pragma unroll
            for (int nt = 0; nt < 8; nt++) {
                int colw = (n0 + nt * 8 + q * 2) >> 1;
                __half2 d0 = __floats2half2_rn(acc[mt][nt][0] * INV_SQRT_H,
                                               acc[mt][nt][1] * INV_SQRT_H);
                __half2 d1 = __floats2half2_rn(acc[mt][nt][2] * INV_SQRT_H,
                                               acc[mt][nt][3] * INV_SQRT_H);
                sB[r * 68 + colw]       = *(unsigned*)&d0;
                sB[(r + 8) * 68 + colw] = *(unsigned*)&d1;
            }
        }
        __syncthreads();
        #pragma unroll
        for (int it = 0; it < 8; it++) {
            int r = wid * 16 + it * 2 + (lane >> 4);
            int cw = lane & 15;
            uint4 v = *(uint4*)&sB[r * 68 + cw * 4];
            *(uint4*)&g_tpw16[(size_t)(e0 + r) * 512 + nh * 128 + cw * 8] = v;
        }
    }
}

// ---------------- node up-projections s, v (planar v output) ----------------
// y=0: s = nf[:, :128] @ Wu0. y=1: all 3 v comps with one X read, vs 3 strided passes.
__global__ __launch_bounds__(256) void k_sv(const float* __restrict__ nf,
                                            const float* __restrict__ Wu0,
                                            const float* __restrict__ Wu1) {
    __shared__ float sW[64 * 128];   // 32 KB
    __shared__ float sX[3 * 32 * 64]; // 24 KB (y=0 uses first plane)
    int t = threadIdx.x;
    int grp = blockIdx.y;            // 0: s, 1: v(3 comps)
    int n0 = blockIdx.x * 32;
    const float* W = (grp == 0) ? Wu0 : Wu1;
    int nb = (t >> 5) << 2, ob = (t & 31) << 2;

    if (grp == 0) {
        float acc[4][4] = {};
        for (int k0 = 0; k0 < CDIM; k0 += 64) {
            __syncthreads();
            for (int i = t; i < 64 * 128; i += 256) {
                int kk = i >> 7, d = i & 127;
                sW[i] = W[(k0 + kk) * 128 + d];
            }
            for (int i = t; i < 32 * 64; i += 256) {
                int r = i >> 6, kk = i & 63;
                int n = n0 + r;
                sX[i] = (n < N_NODES) ? nf[n * 512 + k0 + kk] : 0.f;
            }
            __syncthreads();
            #pragma unroll
            for (int kk = 0; kk < 64; kk++) {
                float a0 = sX[(nb + 0) * 64 + kk];
                float a1 = sX[(nb + 1) * 64 + kk];
                float a2 = sX[(nb + 2) * 64 + kk];
                float a3 = sX[(nb + 3) * 64 + kk];
                float4 w = *(const float4*)&sW[kk * 128 + ob];
                acc[0][0] += a0 * w.x; acc[0][1] += a0 * w.y; acc[0][2] += a0 * w.z; acc[0][3] += a0 * w.w;
                acc[1][0] += a1 * w.x; acc[1][1] += a1 * w.y; acc[1][2] += a1 * w.z; acc[1][3] += a1 * w.w;
                acc[2][0] += a2 * w.x; acc[2][1] += a2 * w.y; acc[2][2] += a2 * w.z; acc[2][3] += a2 * w.w;
                acc[3][0] += a3 * w.x; acc[3][1] += a3 * w.y; acc[3][2] += a3 * w.z; acc[3][3] += a3 * w.w;
            }
        }
        #pragma unroll
        for (int r = 0; r < 4; r++) {
            int n = n0 + nb + r;
            if (n >= N_NODES) continue;
            *(float4*)&g_s[n * 128 + ob] =
                make_float4(acc[r][0] * INV_SQRT_C, acc[r][1] * INV_SQRT_C,
                            acc[r][2] * INV_SQRT_C, acc[r][3] * INV_SQRT_C);
        }
    } else {
        float acc[3][4][4] = {};
        for (int k0 = 0; k0 < CDIM; k0 += 64) {
            __syncthreads();
            for (int i = t; i < 64 * 128; i += 256) {
                int kk = i >> 7, d = i & 127;
                sW[i] = W[(k0 + kk) * 128 + d];
            }
            // read contiguous v-region once, scatter into 3 comp planes
            for (int i = t; i < 32 * 192; i += 256) {
                int n = i / 192, j = i % 192;
                int kk = j / 3, cm = j % 3;
                int node = n0 + n;
                float v = (node < N_NODES) ? nf[node * 512 + 128 + 3 * k0 + j] : 0.f;
                sX[cm * 2048 + n * 64 + kk] = v;
            }
            __syncthreads();
            #pragma unroll
            for (int kk = 0; kk < 64; kk++) {
                float4 w = *(const float4*)&sW[kk * 128 + ob];
                #pragma unroll
                for (int cm = 0; cm < 3; cm++) {
                    const float* xp = &sX[cm * 2048];
                    float a0 = xp[(nb + 0) * 64 + kk];
                    float a1 = xp[(nb + 1) * 64 + kk];
                    float a2 = xp[(nb + 2) * 64 + kk];
                    float a3 = xp[(nb + 3) * 64 + kk];
                    acc[cm][0][0] += a0 * w.x; acc[cm][0][1] += a0 * w.y; acc[cm][0][2] += a0 * w.z; acc[cm][0][3] += a0 * w.w;
                    acc[cm][1][0] += a1 * w.x; acc[cm][1][1] += a1 * w.y; acc[cm][1][2] += a1 * w.z; acc[cm][1][3] += a1 * w.w;
                    acc[cm][2][0] += a2 * w.x; acc[cm][2][1] += a2 * w.y; acc[cm][2][2] += a2 * w.z; acc[cm][2][3] += a2 * w.w;
                    acc[cm][3][0] += a3 * w.x; acc[cm][3][1] += a3 * w.y; acc[cm][3][2] += a3 * w.z; acc[cm][3][3] += a3 * w.w;
                }
            }
        }
        #pragma unroll
        for (int cm = 0; cm < 3; cm++)
            #pragma unroll
            for (int r = 0; r < 4; r++) {
                int n = n0 + nb + r;
                if (n >= N_NODES) continue;
                *(float4*)&g_v[n * 384 + cm * 128 + ob] =
                    make_float4(acc[cm][r][0] * INV_SQRT_C, acc[cm][r][1] * INV_SQRT_C,
                                acc[cm][r][2] * INV_SQRT_C, acc[cm][r][3] * INV_SQRT_C);
            }
    }
}

// ---------------- fused weights: WcT[a][col][k] = (W_lin @ W_skip[:,a,:])^T, fp16 ----------------
__global__ __launch_bounds__(256) void k_wc(const float* __restrict__ Wl0,
                                            const float* __restrict__ Wl1,
                                            const float* __restrict__ Wsk0,
                                            const float* __restrict__ Wsk1) {
    __shared__ float sSk[64 * 128];  // 32 KB
    __shared__ float sWl[16 * 64];   // 4 KB
    int t = threadIdx.x;
    int c0 = blockIdx.x * 16;
    int a = blockIdx.y;
    int pair = blockIdx.z;
    const float* Wl  = pair ? Wl1  : Wl0;
    const float* Wsk = pair ? Wsk1 : Wsk0;
    __half* WcT = pair ? g_WcT1 : g_WcT0;
    int d = t & 127, half = t >> 7;
    float acc[8] = {};
    for (int m0 = 0; m0 < 128; m0 += 64) {
        __syncthreads();
        for (int i = t; i < 64 * 128; i += 256) {
            int mm = i >> 7, dd = i & 127;
            sSk[i] = Wsk[((m0 + mm) * ADIM + a) * 128 + dd];
        }
        for (int i = t; i < 16 * 64; i += 256) {
            int cc = i >> 6, mm = i & 63;
            sWl[i] = Wl[(c0 + cc) * 128 + m0 + mm];
        }
        __syncthreads();
        #pragma unroll 8
        for (int m = 0; m < 64; m++) {
            float sk = sSk[m * 128 + d];
            #pragma unroll
            for (int j = 0; j < 8; j++) {
                int cc = half + 2 * j;
                acc[j] = fmaf(sWl[cc * 64 + m], sk, acc[j]);
            }
        }
    }
    #pragma unroll
    for (int j = 0; j < 8; j++) {
        int c = c0 + half + 2 * j;   // k index 0..255
        WcT[(a * 128 + d) * 256 + c] = __float2half_rn(acc[j]);
    }
}

// ---------------- edge aggregation: 2 nodes/CTA, half2/float2 vectorized ----------------
__global__ __launch_bounds__(128) void k_agg(const int* __restrict__ sender,
                                             const float* __restrict__ ea) {
    int t = threadIdx.x;
    int n = blockIdx.x * 2 + (t >> 6);        // N_NODES even
    int c2 = t & 63;                          // channels 2*c2, 2*c2+1
    int beg = g_off[n], end = g_off[n + 1];

    float2 ms1 = {0, 0}, ms2 = {0, 0};
    float2 mv10 = {0, 0}, mv11 = {0, 0}, mv12 = {0, 0};
    float2 mv20 = {0, 0}, mv21 = {0, 0}, mv22 = {0, 0};

    for (int p = beg; p < end; p++) {
        int e = g_csr[p];
        int sj = sender[e];
        float4 y = *(const float4*)&ea[e * 4];
        const __half2* tw = (const __half2*)(g_tpw16 + (size_t)e * 512);
        float2 ws1 = __half22float2(tw[c2]);
        float2 ws2 = __half22float2(tw[64 + c2]);
        float2 wv1 = __half22float2(tw[128 + c2]);
        float2 wv2 = __half22float2(tw[192 + c2]);
        float2 sv = *(const float2*)&g_s[sj * 128 + 2 * c2];
        const float* vb = &g_v[sj * 384 + 2 * c2];
        float2 v0 = *(const float2*)(vb);
        float2 v1 = *(const float2*)(vb + 128);
        float2 v2 = *(const float2*)(vb + 256);

        ms1.x = fmaf(ws1.x * sv.x, y.x, ms1.x);
        ms1.y = fmaf(ws1.y * sv.y, y.x, ms1.y);
        float dx = v0.x * y.y + v1.x * y.z + v2.x * y.w;
        float dy = v0.y * y.y + v1.y * y.z + v2.y * y.w;
        ms2.x = fmaf(ws2.x, dx, ms2.x);
        ms2.y = fmaf(ws2.y, dy, ms2.y);
        float a1x = wv1.x * sv.x, a1y = wv1.y * sv.y;
        mv10.x = fmaf(a1x, y.y, mv10.x); mv10.y = fmaf(a1y, y.y, mv10.y);
        mv11.x = fmaf(a1x, y.z, mv11.x); mv11.y = fmaf(a1y, y.z, mv11.y);
        mv12.x = fmaf(a1x, y.w, mv12.x); mv12.y = fmaf(a1y, y.w, mv12.y);
        float a2x = wv2.x * y.x, a2y = wv2.y * y.x;
        mv20.x = fmaf(a2x, v0.x, mv20.x); mv20.y = fmaf(a2y, v0.y, mv20.y);
        mv21.x = fmaf(a2x, v1.x, mv21.x); mv21.y = fmaf(a2y, v1.y, mv21.y);
        mv22.x = fmaf(a2x, v2.x, mv22.x); mv22.y = fmaf(a2y, v2.y, mv22.y);
    }

    __half2* M = (__half2*)g_M16;
    const int PL2 = N_NODES * 128;
    M[n * 128 + c2]            = __floats2half2_rn(ms1.x, ms1.y);
    M[n * 128 + 64 + c2]       = __floats2half2_rn(ms2.x * INV_SQRT3, ms2.y * INV_SQRT3);
    M[PL2 + n * 128 + c2]      = __floats2half2_rn(mv10.x, mv10.y);
    M[PL2 + n * 128 + 64 + c2] = __floats2half2_rn(mv20.x, mv20.y);
    M[2*PL2 + n * 128 + c2]      = __floats2half2_rn(mv11.x, mv11.y);
    M[2*PL2 + n * 128 + 64 + c2] = __floats2half2_rn(mv21.x, mv21.y);
    M[3*PL2 + n * 128 + c2]      = __floats2half2_rn(mv12.x, mv12.y);
    M[3*PL2 + n * 128 + 64 + c2] = __floats2half2_rn(mv22.x, mv22.y);
}

// ---------------- class-batched output GEMM via fp16 mma (verified R14, unchanged) ----
__global__ __launch_bounds__(128) void k_final(float* __restrict__ out) {
    __shared__ __align__(16) unsigned sA[64 * 36];
    __shared__ __align__(16) unsigned sB[128 * 36];
    __shared__ int sN[64];
    unsigned sbA = smem_u32(sA), sbB = smem_u32(sB);

    int t = threadIdx.x, lane = t & 31, wid = t >> 5;
    int comp = blockIdx.y;
    int row0 = blockIdx.x * 64;
    if (row0 >= g_pcoff[ADIM]) return;
    int a = 0;
    while (row0 >= g_pcoff[a + 1]) a++;

    if (t < 64) sN[t] = g_clistp[row0 + t];
    __syncthreads();

    const uint4* M = (const uint4*)g_M16 + (size_t)comp * (N_NODES * 32);
    const uint4* B = (const uint4*)(comp == 0 ? g_WcT0 : g_WcT1) + a * 128 * 32;

    int g = lane >> 2, q = lane & 3;
    int m0 = (wid >> 1) * 32;
    int n0 = (wid & 1) * 64;
    unsigned aoff = (unsigned)((lane & 15) * 144 + ((lane >> 4) << 4)) + m0 * 144;
    unsigned boff = (unsigned)((((lane >> 4) << 3) + (lane & 7)) * 144 + (((lane >> 3) & 1) << 4)) + n0 * 144;
    unsigned Ab = sbA + aoff;
    unsigned Bb = sbB + boff;

    float acc[2][8][4];
    #pragma unroll
    for (int mt = 0; mt < 2; mt++)
        #pragma unroll
        for (int nt = 0; nt < 8; nt++)
            #pragma unroll
            for (int j = 0; j < 4; j++) acc[mt][nt][j] = 0.f;

    for (int kc = 0; kc < 4; kc++) {
        __syncthreads();
        for (int i = t; i < 64 * 8; i += 128) {
            int row = i >> 3, u = i & 7;
            int node = sN[row];
            uint4 v = make_uint4(0, 0, 0, 0);
            if (node >= 0) v = M[node * 32 + kc * 8 + u];
            *(uint4*)&sA[row * 36 + u * 4] = v;
        }
        for (int i = t; i < 128 * 8; i += 128) {
            int col = i >> 3, u = i & 7;
            uint4 v = B[col * 32 + kc * 8 + u];
            *(uint4*)&sB[col * 36 + u * 4] = v;
        }
        __syncthreads();

        #pragma unroll
        for (int kt = 0; kt < 4; kt++) {
            unsigned af[2][4];
            #pragma unroll
            for (int mt = 0; mt < 2; mt++)
                LDSM4(af[mt][0], af[mt][1], af[mt][2], af[mt][3], Ab + mt * 2304 + kt * 32);
            #pragma unroll
            for (int j = 0; j < 4; j++) {
                unsigned bf[4];
                LDSM4(bf[0], bf[1], bf[2], bf[3], Bb + j * 2304 + kt * 32);
                #pragma unroll
                for (int h = 0; h < 2; h++) {
                    int nt = j * 2 + h;
                    #pragma unroll
                    for (int mt = 0; mt < 2; mt++)
                        MMA16816(acc[mt][nt], af[mt][0], af[mt][1], af[mt][2], af[mt][3],
                                 bf[h * 2], bf[h * 2 + 1]);
                }
            }
        }
    }

    #pragma unroll
    for (int mt = 0; mt < 2; mt++) {
        int r = m0 + mt * 16 + g;
        int nodeA = sN[r], nodeB = sN[r + 8];
        #pragma unroll
        for (int nt = 0; nt < 8; nt++) {
            int col = n0 + nt * 8 + q * 2;
            if (comp == 0) {
                if (nodeA >= 0)
                    *(float2*)&out[nodeA * 512 + col] =
                        make_float2(acc[mt][nt][0] * OUT_SCALE, acc[mt][nt][1] * OUT_SCALE);
                if (nodeB >= 0)
                    *(float2*)&out[nodeB * 512 + col] =
                        make_float2(acc[mt][nt][2] * OUT_SCALE, acc[mt][nt][3] * OUT_SCALE);
            } else {
                int cb = 128 + (comp - 1);
                if (nodeA >= 0) {
                    out[nodeA * 512 + cb + col * 3]       = acc[mt][nt][0] * OUT_SCALE;
                    out[nodeA * 512 + cb + (col + 1) * 3] = acc[mt][nt][1] * OUT_SCALE;
                }
                if (nodeB >= 0) {
                    out[nodeB * 512 + cb + col * 3]       = acc[mt][nt][2] * OUT_SCALE;
                    out[nodeB * 512 + cb + (col + 1) * 3] = acc[mt][nt][3] * OUT_SCALE;
                }
            }
        }
    }
}

// ---------------- launch ----------------
extern "C" void kernel_launch(void* const* d_in, const int* in_sizes, int n_in,
                              void* d_out, int out_size) {
    const float* node_attrs = (const float*)d_in[0];
    const float* node_feats = (const float*)d_in[1];
    const float* edge_attrs = (const float*)d_in[2];
    const float* edge_feats = (const float*)d_in[3];
    const int*   edge_index = (const int*)d_in[4];
    const float* W_up0  = (const float*)d_in[5];
    const float* W_up1  = (const float*)d_in[6];
    const float* W_mlp1 = (const float*)d_in[7];
    const float* W_mlp2 = (const float*)d_in[8];
    const float* W_mlp3 = (const float*)d_in[9];
    const float* W_mlp4 = (const float*)d_in[10];
    const float* W_lin0 = (const float*)d_in[11];
    const float* W_lin1 = (const float*)d_in[12];
    const float* W_skip0 = (const float*)d_in[13];
    const float* W_skip1 = (const float*)d_in[14];
    float* out = (float*)d_out;

    const int* sender = edge_index;            // row 0
    const int* recv   = edge_index + N_EDGES;  // row 1

    // Launch order: k_tpw kept at slot 4 (ncu capture slot).
    k_w4t<<<144, 256>>>(W_mlp4, W_mlp2, W_mlp3);                     // 1
    k_cls<<<(NPAD + 255) / 256, 256>>>(node_attrs);                  // 2
    k_mlp<<<N_EDGES / 64, 128>>>(edge_feats, W_mlp1);                // 3  (tensor core)
    k_tpw<<<N_EDGES / 64, 128>>>();                                  // 4  (tensor core)
    k_count<<<N_EDGES / 256, 256>>>(recv);                           // 5
    k_sv<<<dim3((N_NODES + 31) / 32, 2), 256>>>(node_feats, W_up0, W_up1); // 6
    k_scan<<<1, 1024>>>();                                           // 7
    k_fill<<<N_EDGES / 256, 256>>>(recv);                            // 8
    k_wc<<<dim3(16, ADIM, 2), 256>>>(W_lin0, W_lin1, W_skip0, W_skip1); // 9
    k_agg<<<N_NODES / 2, 128>>>(sender, edge_attrs);                 // 10
    k_final<<<dim3((NPAD + 63) / 64, 4), 128>>>(out);                // 11 (tensor core)
}